// round 1
// baseline (speedup 1.0000x reference)
#include <cuda_runtime.h>
#include <cuda_bf16.h>
#include <math.h>

#define NB 4
#define NN 4096
#define CCH 8

// ---------------- device global scratch (no allocation allowed) ----------------
// 14 paths: 0-5 VAL, 6-13 OUT. Max tensor 13*13*13 = 2197 floats.
__device__ float g_w3j[14][2197];
__device__ float g_M[8][3];
__device__ float g_pb[NN];
__device__ float g_qk[NB][NN][24];   // 22 used (sqrt(s4)*f4n | sqrt(s6)*f6n), padded
__device__ float g_rv[NB][NN][68];   // 66 used, padded
__device__ float g_ctx[NB][NN][68];  // 66 used

// path tables
__constant__ int c_VAL_L[6][3] = {{4,0,4},{4,2,4},{6,2,4},{4,2,6},{6,0,6},{6,2,6}};
__constant__ int c_OUT_L[8][3] = {{4,4,4},{4,6,4},{6,4,4},{6,6,4},{4,4,6},{4,6,6},{6,4,6},{6,6,6}};
__constant__ int c_RVOFF[6] = {0,9,18,27,40,53};
// packed offsets for OUT w3j in shared (sizes 729,1053,1053,1521,1053,1521,1521,2197)
__constant__ int c_OUT_OFF[8] = {0,729,1782,2835,4356,5409,6930,8451};   // total 10648
__constant__ int c_VAL_OFF[6] = {0,81,486,1071,1656,1825};               // sizes 81,405,585,585,169,845 tot 2670
__constant__ int c_VAL_SZ[6]  = {81,405,585,585,169,845};
__constant__ int c_OUT_SZ[8]  = {729,1053,1053,1521,1053,1521,1521,2197};

// ---------------- init: Wigner 3j tensors (fp64 on device) ----------------
__device__ double d_cg(int l1,int l2,int l3,int m1,int m2,int m3,const double* F){
    if (m1+m2 != m3) return 0.0;
    double pref = sqrt((2.0*l3+1.0)*F[l3+l1-l2]*F[l3-l1+l2]*F[l1+l2-l3]/F[l1+l2+l3+1]);
    pref *= sqrt(F[l3+m3]*F[l3-m3]*F[l1-m1]*F[l1+m1]*F[l2-m2]*F[l2+m2]);
    double s = 0.0;
    for (int k = 0; k <= l1+l2-l3; k++){
        int d0=k, d1=l1+l2-l3-k, d2=l1-m1-k, d3=l2+m2-k, d4=l3-l2+m1+k, d5=l3-l1-m2+k;
        if (d0<0||d1<0||d2<0||d3<0||d4<0||d5<0) continue;
        double den = F[d0]*F[d1]*F[d2]*F[d3]*F[d4]*F[d5];
        s += ((k&1)? -1.0:1.0)/den;
    }
    return pref*s;
}

__device__ void build_q(int l, double2* q){
    int L = 2*l+1;
    for (int i=0;i<L*L;i++) q[i] = make_double2(0.0,0.0);
    double rs2 = 1.0/sqrt(2.0);
    for (int m=-l;m<0;m++){
        q[(l+m)*L + (l-m)] = make_double2(rs2, 0.0);     // col l+|m|
        q[(l+m)*L + (l+m)] = make_double2(0.0, -rs2);    // col l-|m|
    }
    q[l*L+l] = make_double2(1.0,0.0);
    for (int m=1;m<=l;m++){
        double sg = (m&1)? -1.0 : 1.0;
        q[(l+m)*L + (l+m)] = make_double2(sg*rs2, 0.0);
        q[(l+m)*L + (l-m)] = make_double2(0.0, sg*rs2);
    }
    double ph = (l % 4 == 0) ? 1.0 : -1.0;  // (-i)^l for even l
    for (int i=0;i<L*L;i++){ q[i].x *= ph; q[i].y *= ph; }
}

__global__ void k_init_w3j(){
    int t = blockIdx.x;
    int l1,l2,l3;
    if (t<6){ l1=c_VAL_L[t][0]; l2=c_VAL_L[t][1]; l3=c_VAL_L[t][2]; }
    else    { l1=c_OUT_L[t-6][0]; l2=c_OUT_L[t-6][1]; l3=c_OUT_L[t-6][2]; }
    int I=2*l1+1, J=2*l2+1, K=2*l3+1;
    int IJK = I*J*K;
    __shared__ double sF[24];
    __shared__ double sCc[2197];
    __shared__ double sCr[2197];
    __shared__ double2 sQ1[169], sQ2[169], sQ3[169];
    __shared__ double sRed[128];
    __shared__ double sScale;
    int tid = threadIdx.x;
    if (tid < 24){ double r=1.0; for (int i=2;i<=tid;i++) r*= (double)i; sF[tid]=r; }
    if (tid==0) build_q(l1,sQ1);
    if (tid==1) build_q(l2,sQ2);
    if (tid==2) build_q(l3,sQ3);
    __syncthreads();
    for (int idx=tid; idx<IJK; idx+=blockDim.x){
        int i = idx/(J*K); int r = idx - i*J*K; int kk = r/K; int m = r - kk*K;
        sCc[idx] = d_cg(l1,l2,l3, i-l1, kk-l2, m-l3, sF);
    }
    __syncthreads();
    for (int idx=tid; idx<IJK; idx+=blockDim.x){
        int j = idx/(J*K); int r = idx - j*J*K; int l = r/K; int n = r - l*K;
        double acc = 0.0;
        for (int i=0;i<I;i++){
            double2 q1 = sQ1[i*I+j];
            if (q1.x==0.0 && q1.y==0.0) continue;
            for (int k2=0;k2<J;k2++){
                double2 q2 = sQ2[k2*J+l];
                if (q2.x==0.0 && q2.y==0.0) continue;
                double px = q1.x*q2.x - q1.y*q2.y;
                double py = q1.x*q2.y + q1.y*q2.x;
                for (int m=0;m<K;m++){
                    double2 q3 = sQ3[m*K+n];
                    if (q3.x==0.0 && q3.y==0.0) continue;
                    double c = sCc[(i*J+k2)*K+m];
                    if (c==0.0) continue;
                    acc += (px*q3.x + py*q3.y)*c;   // Re(p * conj(q3)) * c
                }
            }
        }
        sCr[idx] = acc;
    }
    __syncthreads();
    double ss = 0.0;
    for (int idx=tid; idx<IJK; idx+=blockDim.x) ss += sCr[idx]*sCr[idx];
    sRed[tid] = ss;
    __syncthreads();
    for (int s=64;s>0;s>>=1){ if (tid<s) sRed[tid]+=sRed[tid+s]; __syncthreads(); }
    if (tid==0){
        double nrm = sqrt(sRed[0]);
        double sc = (t<6)? sqrt((double)K/(3.0*CCH)) : sqrt((double)K/(4.0*CCH*CCH));
        sScale = sc/nrm;
    }
    __syncthreads();
    for (int idx=tid; idx<IJK; idx+=blockDim.x)
        g_w3j[t][idx] = (float)(sCr[idx]*sScale);
}

// ---------------- init: M[p][qq] absorbing w_out, w_lin_in, w_lin_out, w_val, 1/sqrt(C) ----------------
__global__ void k_init_small(const float* __restrict__ w_lin_in, const float* __restrict__ w_val,
                             const float* __restrict__ w_out, const float* __restrict__ w_lin_out){
    int tid = threadIdx.x;
    if (tid < 24){
        int p = tid/3, qq = tid - p*3;
        int l1o = c_OUT_L[p][0], l2o = c_OUT_L[p][1], l3o = c_OUT_L[p][2];
        const float* wli_p = w_lin_in + (l1o==4 ? 0 : 8);
        const float* wlo   = w_lin_out + (l3o==4 ? 0 : 8);
        int q = (l2o==4 ? 0 : 3) + qq;
        const float* wli_q = w_lin_in + (c_VAL_L[q][0]==4 ? 0 : 8);
        float m = 0.f;
        for (int v=0; v<8; v++){
            float cpv = 0.f;
            for (int u=0; u<8; u++){
                float wu = wli_p[u];
                const float* wo = w_out + ((p*8+u)*8+v)*8;
                for (int w=0; w<8; w++) cpv += wu * wo[w] * wlo[w];
            }
            float aqv = 0.f;
            for (int u=0; u<8; u++) aqv += wli_q[u]*w_val[(q*8+u)*8+v];
            m += cpv*aqv;
        }
        g_M[p][qq] = m * 0.35355339059327373f;  // 1/sqrt(C)
    }
}

// ---------------- prep: per-node qk features, pb, 66-dim rv ----------------
__global__ void k_prep(const float* __restrict__ feat, const float* __restrict__ sh_lr,
                       const float* __restrict__ log_s, const float* __restrict__ pos_w,
                       const float* __restrict__ pos_b){
    __shared__ float sW[2670];                  // packed VAL w3j
    __shared__ float sFt[8][22];
    __shared__ float sY[8][6];
    int tid = threadIdx.x, warp = tid>>5, lane = tid&31;
    for (int p=0;p<6;p++)
        for (int i=tid;i<c_VAL_SZ[p];i+=blockDim.x) sW[c_VAL_OFF[p]+i] = g_w3j[p][i];
    int node = blockIdx.x*8 + warp;
    int b = node >> 12, n = node & (NN-1);
    const float* f = feat + ((size_t)b*NN + n)*22;
    if (lane < 22) sFt[warp][lane] = f[lane];
    if (lane < 6)  sY[warp][lane]  = sh_lr[n*6+lane];
    __syncthreads();
    float n4=0.f, n6=0.f;
    #pragma unroll
    for (int d=0; d<9; d++){ float v=sFt[warp][d]; n4 += v*v; }
    #pragma unroll
    for (int d=9; d<22; d++){ float v=sFt[warp][d]; n6 += v*v; }
    float s4 = __expf(log_s[0]), s6 = __expf(log_s[1]);
    float r4 = sqrtf(s4)/fmaxf(sqrtf(n4), 1e-12f);
    float r6 = sqrtf(s6)/fmaxf(sqrtf(n6), 1e-12f);
    float* qk = &g_qk[b][n][0];
    if (lane < 9)        qk[lane] = sFt[warp][lane]*r4;
    else if (lane < 22)  qk[lane] = sFt[warp][lane]*r6;
    else if (lane < 24)  qk[lane] = 0.f;
    if (b==0 && lane==0){
        float pb = pos_b[0];
        for (int j=0;j<6;j++) pb += sY[warp][j]*pos_w[j];
        g_pb[n] = pb;
    }
    float* rv = &g_rv[b][n][0];
    for (int t=lane; t<68; t+=32){
        if (t >= 66){ rv[t] = 0.f; continue; }
        int p,k;
        if (t < 27){ p = t/9; k = t - p*9; } else { int u=t-27; p = 3 + u/13; k = u - (p-3)*13; }
        int l1 = c_VAL_L[p][0], l2 = c_VAL_L[p][1];
        int I = 2*l1+1, J = 2*l2+1, K = 2*c_VAL_L[p][2]+1;
        int foff = (l1==4)? 0 : 9;
        const float* w = sW + c_VAL_OFF[p];
        float r = 0.f;
        if (J == 1){
            float y0 = sY[warp][0];
            for (int i=0;i<I;i++) r += sFt[warp][foff+i]*y0*w[i*K+k];
        } else {
            for (int i=0;i<I;i++){
                float fi = sFt[warp][foff+i];
                #pragma unroll
                for (int j=0;j<5;j++) r += fi*sY[warp][1+j]*w[(i*5+j)*K+k];
            }
        }
        rv[t] = r;
    }
}

// ---------------- flash attention: ctx_r = softmax(qk·qk^T + pb_j) @ rv ----------------
__global__ void __launch_bounds__(256,2) k_flash(){
    int b = blockIdx.y;
    int q0 = blockIdx.x*32;
    int tid = threadIdx.x, warp = tid>>5, lane = tid&31;
    __shared__ float sQ[32][24];
    __shared__ float sK[64][25];   // padded stride 25 -> conflict-free transposed reads
    __shared__ float sV[64][68];
    __shared__ float sPB[64];
    for (int idx=tid; idx<32*24; idx+=256){ int r=idx/24, d=idx-r*24; sQ[r][d]=g_qk[b][q0+r][d]; }
    float mx[4]   = {-1e30f,-1e30f,-1e30f,-1e30f};
    float ssum[4] = {0.f,0.f,0.f,0.f};
    float acc[4][3] = {};
    const unsigned FULL = 0xffffffffu;
    for (int k0=0; k0<NN; k0+=64){
        for (int idx=tid; idx<64*24; idx+=256){ int r=idx/24, d=idx-r*24; sK[r][d]=g_qk[b][k0+r][d]; }
        for (int idx=tid; idx<64*68; idx+=256){ int r=idx/68, d=idx-r*68; sV[r][d]=g_rv[b][k0+r][d]; }
        if (tid < 64) sPB[tid] = g_pb[k0+tid];
        __syncthreads();
        #pragma unroll
        for (int h=0; h<2; h++){
            int kb = h*32;
            float kr[22];
            #pragma unroll
            for (int d=0; d<22; d++) kr[d] = sK[kb+lane][d];
            float sc[4];
            float pbj = sPB[kb+lane];
            #pragma unroll
            for (int q=0; q<4; q++){
                float s = pbj;
                #pragma unroll
                for (int d=0; d<22; d++) s += sQ[warp*4+q][d]*kr[d];
                sc[q] = s;
            }
            float p[4];
            #pragma unroll
            for (int q=0; q<4; q++){
                float cm = sc[q];
                #pragma unroll
                for (int off=16; off>0; off>>=1) cm = fmaxf(cm, __shfl_xor_sync(FULL, cm, off));
                float mn = fmaxf(mx[q], cm);
                float corr = __expf(mx[q]-mn);
                mx[q] = mn;
                p[q] = __expf(sc[q]-mn);
                ssum[q] = ssum[q]*corr + p[q];
                acc[q][0]*=corr; acc[q][1]*=corr; acc[q][2]*=corr;
            }
            #pragma unroll 8
            for (int kk=0; kk<32; kk++){
                float p0 = __shfl_sync(FULL, p[0], kk);
                float p1 = __shfl_sync(FULL, p[1], kk);
                float p2 = __shfl_sync(FULL, p[2], kk);
                float p3 = __shfl_sync(FULL, p[3], kk);
                float v0 = sV[kb+kk][lane];
                float v1 = sV[kb+kk][32+lane];
                acc[0][0]+=p0*v0; acc[1][0]+=p1*v0; acc[2][0]+=p2*v0; acc[3][0]+=p3*v0;
                acc[0][1]+=p0*v1; acc[1][1]+=p1*v1; acc[2][1]+=p2*v1; acc[3][1]+=p3*v1;
                if (lane < 2){
                    float v2 = sV[kb+kk][64+lane];
                    acc[0][2]+=p0*v2; acc[1][2]+=p1*v2; acc[2][2]+=p2*v2; acc[3][2]+=p3*v2;
                }
            }
        }
        __syncthreads();
    }
    #pragma unroll
    for (int q=0; q<4; q++){
        float t = ssum[q];
        #pragma unroll
        for (int off=16; off>0; off>>=1) t += __shfl_xor_sync(FULL, t, off);
        float inv = 1.0f/t;
        int n = q0 + warp*4 + q;
        g_ctx[b][n][lane]    = acc[q][0]*inv;
        g_ctx[b][n][32+lane] = acc[q][1]*inv;
        if (lane < 2) g_ctx[b][n][64+lane] = acc[q][2]*inv;
    }
}

// ---------------- out: d[k] = sum_p sum_{i,j} f[i] e_p[j] W3Jout[i,j,k] ----------------
template<int I,int J,int K>
__device__ __forceinline__ float path_term(const float* fp, const float* c0, const float* c1, const float* c2,
                                           float m0, float m1, float m2, const float* w, int k){
    float e[J];
    #pragma unroll
    for (int j=0;j<J;j++) e[j] = m0*c0[j] + m1*c1[j] + m2*c2[j];
    float d = 0.f;
    for (int i=0;i<I;i++){
        float fi = fp[i];
        #pragma unroll
        for (int j=0;j<J;j++) d += fi*e[j]*w[(i*J+j)*K+k];
    }
    return d;
}

__global__ void k_out(const float* __restrict__ feat, float* __restrict__ out){
    __shared__ float sW[10648];     // packed OUT w3j
    __shared__ float sFt[8][22];
    __shared__ float sC[8][66];
    int tid = threadIdx.x, warp = tid>>5, lane = tid&31;
    for (int p=0;p<8;p++)
        for (int i=tid;i<c_OUT_SZ[p];i+=blockDim.x) sW[c_OUT_OFF[p]+i] = g_w3j[6+p][i];
    int node = blockIdx.x*8 + warp;
    int b = node >> 12, n = node & (NN-1);
    if (lane < 22) sFt[warp][lane] = feat[((size_t)b*NN+n)*22 + lane];
    for (int t=lane; t<66; t+=32) sC[warp][t] = g_ctx[b][n][t];
    __syncthreads();
    if (lane < 22){
        const float* F = sFt[warp];
        const float* C = sC[warp];
        float d;
        if (lane < 9){
            int k = lane;
            d  = path_term<9 ,9 ,9>(F  , C   , C+9 , C+18, g_M[0][0],g_M[0][1],g_M[0][2], sW+c_OUT_OFF[0], k);
            d += path_term<9 ,13,9>(F  , C+27, C+40, C+53, g_M[1][0],g_M[1][1],g_M[1][2], sW+c_OUT_OFF[1], k);
            d += path_term<13,9 ,9>(F+9, C   , C+9 , C+18, g_M[2][0],g_M[2][1],g_M[2][2], sW+c_OUT_OFF[2], k);
            d += path_term<13,13,9>(F+9, C+27, C+40, C+53, g_M[3][0],g_M[3][1],g_M[3][2], sW+c_OUT_OFF[3], k);
        } else {
            int k = lane - 9;
            d  = path_term<9 ,9 ,13>(F  , C   , C+9 , C+18, g_M[4][0],g_M[4][1],g_M[4][2], sW+c_OUT_OFF[4], k);
            d += path_term<9 ,13,13>(F  , C+27, C+40, C+53, g_M[5][0],g_M[5][1],g_M[5][2], sW+c_OUT_OFF[5], k);
            d += path_term<13,9 ,13>(F+9, C   , C+9 , C+18, g_M[6][0],g_M[6][1],g_M[6][2], sW+c_OUT_OFF[6], k);
            d += path_term<13,13,13>(F+9, C+27, C+40, C+53, g_M[7][0],g_M[7][1],g_M[7][2], sW+c_OUT_OFF[7], k);
        }
        out[((size_t)b*NN+n)*22 + lane] = d;
    }
}

// ---------------- launch ----------------
extern "C" void kernel_launch(void* const* d_in, const int* in_sizes, int n_in,
                              void* d_out, int out_size){
    const float* feat      = (const float*)d_in[0];
    const float* sh_lr     = (const float*)d_in[1];
    const float* log_s     = (const float*)d_in[2];
    const float* pos_w     = (const float*)d_in[3];
    const float* pos_b     = (const float*)d_in[4];
    const float* w_lin_in  = (const float*)d_in[5];
    const float* w_val     = (const float*)d_in[6];
    const float* w_out     = (const float*)d_in[7];
    const float* w_lin_out = (const float*)d_in[8];
    float* out = (float*)d_out;

    k_init_w3j<<<14,128>>>();
    k_init_small<<<1,32>>>(w_lin_in, w_val, w_out, w_lin_out);
    k_prep<<<(NB*NN)/8, 256>>>(feat, sh_lr, log_s, pos_w, pos_b);
    dim3 g(NN/32, NB);
    k_flash<<<g, 256>>>();
    k_out<<<(NB*NN)/8, 256>>>(feat, out);
}

// round 2
// speedup vs baseline: 1.3903x; 1.3903x over previous
#include <cuda_runtime.h>
#include <cuda_bf16.h>
#include <math.h>

#define NB 4
#define NN 4096
#define CCH 8
#define KSPLIT 8
#define KCH 64

typedef unsigned long long ull;

__device__ __forceinline__ void fma2(ull& d, ull a, ull b){
    asm("fma.rn.f32x2 %0, %1, %2, %0;" : "+l"(d) : "l"(a), "l"(b));
}

// ---------------- device global scratch ----------------
__device__ float g_w3j[14][2197];
__device__ float g_M[8][3];
__device__ float g_pb[NN];
__device__ float g_qk[NB][NN][24];            // 22 used, padded to 24 (96B rows)
__device__ float g_rv[NB][NN][68];            // 66 used, padded to 68 (272B rows)
__device__ float g_ctx[NB][NN][68];           // 66 used
__device__ float g_part[KSPLIT][NB][NN][68];  // 66 acc + ssum at [66]
__device__ float g_inv[NB*NN];

__constant__ int c_VAL_L[6][3] = {{4,0,4},{4,2,4},{6,2,4},{4,2,6},{6,0,6},{6,2,6}};
__constant__ int c_OUT_L[8][3] = {{4,4,4},{4,6,4},{6,4,4},{6,6,4},{4,4,6},{4,6,6},{6,4,6},{6,6,6}};
__constant__ int c_OUT_OFF[8] = {0,729,1782,2835,4356,5409,6930,8451};
__constant__ int c_VAL_OFF[6] = {0,81,486,1071,1656,1825};
__constant__ int c_VAL_SZ[6]  = {81,405,585,585,169,845};
__constant__ int c_OUT_SZ[8]  = {729,1053,1053,1521,1053,1521,1521,2197};

// ---------------- init: Wigner 3j tensors (fp64 on device) ----------------
__device__ double d_cg(int l1,int l2,int l3,int m1,int m2,int m3,const double* F){
    if (m1+m2 != m3) return 0.0;
    double pref = sqrt((2.0*l3+1.0)*F[l3+l1-l2]*F[l3-l1+l2]*F[l1+l2-l3]/F[l1+l2+l3+1]);
    pref *= sqrt(F[l3+m3]*F[l3-m3]*F[l1-m1]*F[l1+m1]*F[l2-m2]*F[l2+m2]);
    double s = 0.0;
    for (int k = 0; k <= l1+l2-l3; k++){
        int d0=k, d1=l1+l2-l3-k, d2=l1-m1-k, d3=l2+m2-k, d4=l3-l2+m1+k, d5=l3-l1-m2+k;
        if (d0<0||d1<0||d2<0||d3<0||d4<0||d5<0) continue;
        double den = F[d0]*F[d1]*F[d2]*F[d3]*F[d4]*F[d5];
        s += ((k&1)? -1.0:1.0)/den;
    }
    return pref*s;
}

__device__ void build_q(int l, double2* q){
    int L = 2*l+1;
    for (int i=0;i<L*L;i++) q[i] = make_double2(0.0,0.0);
    double rs2 = 1.0/sqrt(2.0);
    for (int m=-l;m<0;m++){
        q[(l+m)*L + (l-m)] = make_double2(rs2, 0.0);
        q[(l+m)*L + (l+m)] = make_double2(0.0, -rs2);
    }
    q[l*L+l] = make_double2(1.0,0.0);
    for (int m=1;m<=l;m++){
        double sg = (m&1)? -1.0 : 1.0;
        q[(l+m)*L + (l+m)] = make_double2(sg*rs2, 0.0);
        q[(l+m)*L + (l-m)] = make_double2(0.0, sg*rs2);
    }
    double ph = (l % 4 == 0) ? 1.0 : -1.0;
    for (int i=0;i<L*L;i++){ q[i].x *= ph; q[i].y *= ph; }
}

__global__ void k_init_w3j(){
    int t = blockIdx.x;
    int l1,l2,l3;
    if (t<6){ l1=c_VAL_L[t][0]; l2=c_VAL_L[t][1]; l3=c_VAL_L[t][2]; }
    else    { l1=c_OUT_L[t-6][0]; l2=c_OUT_L[t-6][1]; l3=c_OUT_L[t-6][2]; }
    int I=2*l1+1, J=2*l2+1, K=2*l3+1;
    int IJK = I*J*K;
    __shared__ double sF[24];
    __shared__ double sCc[2197];
    __shared__ double sCr[2197];
    __shared__ double2 sQ1[169], sQ2[169], sQ3[169];
    __shared__ double sRed[128];
    __shared__ double sScale;
    int tid = threadIdx.x;
    if (tid < 24){ double r=1.0; for (int i=2;i<=tid;i++) r*= (double)i; sF[tid]=r; }
    if (tid==0) build_q(l1,sQ1);
    if (tid==1) build_q(l2,sQ2);
    if (tid==2) build_q(l3,sQ3);
    __syncthreads();
    for (int idx=tid; idx<IJK; idx+=blockDim.x){
        int i = idx/(J*K); int r = idx - i*J*K; int kk = r/K; int m = r - kk*K;
        sCc[idx] = d_cg(l1,l2,l3, i-l1, kk-l2, m-l3, sF);
    }
    __syncthreads();
    for (int idx=tid; idx<IJK; idx+=blockDim.x){
        int j = idx/(J*K); int r = idx - j*J*K; int l = r/K; int n = r - l*K;
        double acc = 0.0;
        for (int i=0;i<I;i++){
            double2 q1 = sQ1[i*I+j];
            if (q1.x==0.0 && q1.y==0.0) continue;
            for (int k2=0;k2<J;k2++){
                double2 q2 = sQ2[k2*J+l];
                if (q2.x==0.0 && q2.y==0.0) continue;
                double px = q1.x*q2.x - q1.y*q2.y;
                double py = q1.x*q2.y + q1.y*q2.x;
                for (int m=0;m<K;m++){
                    double2 q3 = sQ3[m*K+n];
                    if (q3.x==0.0 && q3.y==0.0) continue;
                    double c = sCc[(i*J+k2)*K+m];
                    if (c==0.0) continue;
                    acc += (px*q3.x + py*q3.y)*c;
                }
            }
        }
        sCr[idx] = acc;
    }
    __syncthreads();
    double ss = 0.0;
    for (int idx=tid; idx<IJK; idx+=blockDim.x) ss += sCr[idx]*sCr[idx];
    sRed[tid] = ss;
    __syncthreads();
    for (int s=64;s>0;s>>=1){ if (tid<s) sRed[tid]+=sRed[tid+s]; __syncthreads(); }
    if (tid==0){
        double nrm = sqrt(sRed[0]);
        double sc = (t<6)? sqrt((double)K/(3.0*CCH)) : sqrt((double)K/(4.0*CCH*CCH));
        sScale = sc/nrm;
    }
    __syncthreads();
    for (int idx=tid; idx<IJK; idx+=blockDim.x)
        g_w3j[t][idx] = (float)(sCr[idx]*sScale);
}

// ---------------- init: M[p][qq] ----------------
__global__ void k_init_small(const float* __restrict__ w_lin_in, const float* __restrict__ w_val,
                             const float* __restrict__ w_out, const float* __restrict__ w_lin_out){
    int tid = threadIdx.x;
    if (tid < 24){
        int p = tid/3, qq = tid - p*3;
        int l1o = c_OUT_L[p][0], l2o = c_OUT_L[p][1], l3o = c_OUT_L[p][2];
        const float* wli_p = w_lin_in + (l1o==4 ? 0 : 8);
        const float* wlo   = w_lin_out + (l3o==4 ? 0 : 8);
        int q = (l2o==4 ? 0 : 3) + qq;
        const float* wli_q = w_lin_in + (c_VAL_L[q][0]==4 ? 0 : 8);
        float m = 0.f;
        for (int v=0; v<8; v++){
            float cpv = 0.f;
            for (int u=0; u<8; u++){
                float wu = wli_p[u];
                const float* wo = w_out + ((p*8+u)*8+v)*8;
                for (int w=0; w<8; w++) cpv += wu * wo[w] * wlo[w];
            }
            float aqv = 0.f;
            for (int u=0; u<8; u++) aqv += wli_q[u]*w_val[(q*8+u)*8+v];
            m += cpv*aqv;
        }
        g_M[p][qq] = m * 0.35355339059327373f;
    }
}

// ---------------- prep ----------------
__global__ void k_prep(const float* __restrict__ feat, const float* __restrict__ sh_lr,
                       const float* __restrict__ log_s, const float* __restrict__ pos_w,
                       const float* __restrict__ pos_b){
    __shared__ float sW[2670];
    __shared__ float sFt[8][22];
    __shared__ float sY[8][6];
    int tid = threadIdx.x, warp = tid>>5, lane = tid&31;
    for (int p=0;p<6;p++)
        for (int i=tid;i<c_VAL_SZ[p];i+=blockDim.x) sW[c_VAL_OFF[p]+i] = g_w3j[p][i];
    int node = blockIdx.x*8 + warp;
    int b = node >> 12, n = node & (NN-1);
    const float* f = feat + ((size_t)b*NN + n)*22;
    if (lane < 22) sFt[warp][lane] = f[lane];
    if (lane < 6)  sY[warp][lane]  = sh_lr[n*6+lane];
    __syncthreads();
    float n4=0.f, n6=0.f;
    #pragma unroll
    for (int d=0; d<9; d++){ float v=sFt[warp][d]; n4 += v*v; }
    #pragma unroll
    for (int d=9; d<22; d++){ float v=sFt[warp][d]; n6 += v*v; }
    float s4 = __expf(log_s[0]), s6 = __expf(log_s[1]);
    float r4 = sqrtf(s4)/fmaxf(sqrtf(n4), 1e-12f);
    float r6 = sqrtf(s6)/fmaxf(sqrtf(n6), 1e-12f);
    float* qk = &g_qk[b][n][0];
    if (lane < 9)        qk[lane] = sFt[warp][lane]*r4;
    else if (lane < 22)  qk[lane] = sFt[warp][lane]*r6;
    else if (lane < 24)  qk[lane] = 0.f;
    if (b==0 && lane==0){
        float pb = pos_b[0];
        for (int j=0;j<6;j++) pb += sY[warp][j]*pos_w[j];
        g_pb[n] = pb;
    }
    float* rv = &g_rv[b][n][0];
    for (int t=lane; t<68; t+=32){
        if (t >= 66){ rv[t] = 0.f; continue; }
        int p,k;
        if (t < 27){ p = t/9; k = t - p*9; } else { int u=t-27; p = 3 + u/13; k = u - (p-3)*13; }
        int l1 = c_VAL_L[p][0], l2 = c_VAL_L[p][1];
        int I = 2*l1+1, J = 2*l2+1, K = 2*c_VAL_L[p][2]+1;
        int foff = (l1==4)? 0 : 9;
        const float* w = sW + c_VAL_OFF[p];
        float r = 0.f;
        if (J == 1){
            float y0 = sY[warp][0];
            for (int i=0;i<I;i++) r += sFt[warp][foff+i]*y0*w[i*K+k];
        } else {
            for (int i=0;i<I;i++){
                float fi = sFt[warp][foff+i];
                #pragma unroll
                for (int j=0;j<5;j++) r += fi*sY[warp][1+j]*w[(i*5+j)*K+k];
            }
        }
        rv[t] = r;
    }
}

// ---------------- flash attention v2: lane = query, no shuffles, no max-tracking ----------------
// Scores bounded (normalized dots * (s4+s6) + small pb), so exp(s) is safe without
// max subtraction; K-split partials combine by plain addition.
__global__ void __launch_bounds__(256,2) k_flash2(){
    __shared__ float sK[KCH][24];
    __shared__ float sV[KCH][68];
    __shared__ float sPB[KCH];
    int b = blockIdx.z, split = blockIdx.y;
    int tid = threadIdx.x;
    int n = blockIdx.x*256 + tid;            // this thread's query

    ull qr[11];
    {
        const ull* qp = (const ull*)&g_qk[b][n][0];
        #pragma unroll
        for (int i=0;i<11;i++) qr[i]=qp[i];
    }
    ull acc[33];
    #pragma unroll
    for (int i=0;i<33;i++) acc[i]=0ull;
    float ssum = 0.f;

    int ks0 = split*(NN/KSPLIT);
    for (int c=0; c<(NN/KSPLIT)/KCH; c++){
        int kbase = ks0 + c*KCH;
        {
            const float4* gk = (const float4*)&g_qk[b][kbase][0];   // KCH*6 float4
            float4* sk4 = (float4*)&sK[0][0];
            #pragma unroll 2
            for (int i=tid; i<KCH*6; i+=256) sk4[i]=gk[i];
            const float4* gv = (const float4*)&g_rv[b][kbase][0];   // KCH*17 float4
            float4* sv4 = (float4*)&sV[0][0];
            #pragma unroll 5
            for (int i=tid; i<KCH*17; i+=256) sv4[i]=gv[i];
            if (tid<KCH) sPB[tid]=g_pb[kbase+tid];
        }
        __syncthreads();
        #pragma unroll 2
        for (int kk=0; kk<KCH; kk++){
            // score: 22-dim dot, two independent f32x2 chains
            const ulonglong2* kr2 = (const ulonglong2*)&sK[kk][0];
            ull s2a = 0ull, s2b = 0ull;
            #pragma unroll
            for (int i=0;i<5;i++){
                ulonglong2 t = kr2[i];
                fma2(s2a, qr[2*i],   t.x);
                fma2(s2b, qr[2*i+1], t.y);
            }
            {
                ull k10 = ((const ull*)&sK[kk][0])[10];
                fma2(s2a, qr[10], k10);
            }
            float a0,a1,b0,b1;
            asm("mov.b64 {%0,%1}, %2;" : "=f"(a0), "=f"(a1) : "l"(s2a));
            asm("mov.b64 {%0,%1}, %2;" : "=f"(b0), "=f"(b1) : "l"(s2b));
            float s = (a0+a1) + (b0+b1) + sPB[kk];
            float p = __expf(s);
            ssum += p;
            ull pp; asm("mov.b64 %0, {%1,%1};" : "=l"(pp) : "f"(p));
            // PV: 66-dim accumulate, f32x2
            const ulonglong2* vr2 = (const ulonglong2*)&sV[kk][0];
            #pragma unroll
            for (int i=0;i<16;i++){
                ulonglong2 t = vr2[i];
                fma2(acc[2*i],   pp, t.x);
                fma2(acc[2*i+1], pp, t.y);
            }
            {
                ull v32 = ((const ull*)&sV[kk][0])[32];
                fma2(acc[32], pp, v32);
            }
        }
        __syncthreads();
    }
    ull* po = (ull*)&g_part[split][b][n][0];
    #pragma unroll
    for (int i=0;i<33;i++) po[i]=acc[i];
    ((float*)po)[66] = ssum;
}

// ---------------- combine K-split partials ----------------
__global__ void k_rsum(){
    int id = blockIdx.x*256 + threadIdx.x;   // 16384
    int b = id>>12, n = id&(NN-1);
    float s=0.f;
    #pragma unroll
    for (int sp=0; sp<KSPLIT; sp++) s += g_part[sp][b][n][66];
    g_inv[id] = 1.f/s;
}

__global__ void k_rctx(){
    int id = blockIdx.x*256 + threadIdx.x;
    if (id >= NB*NN*66) return;
    int node = id/66; int d = id - node*66;
    int b = node>>12, n = node&(NN-1);
    float s=0.f;
    #pragma unroll
    for (int sp=0; sp<KSPLIT; sp++) s += g_part[sp][b][n][d];
    g_ctx[b][n][d] = s*g_inv[node];
}

// ---------------- out ----------------
template<int I,int J,int K>
__device__ __forceinline__ float path_term(const float* fp, const float* c0, const float* c1, const float* c2,
                                           float m0, float m1, float m2, const float* w, int k){
    float e[J];
    #pragma unroll
    for (int j=0;j<J;j++) e[j] = m0*c0[j] + m1*c1[j] + m2*c2[j];
    float d = 0.f;
    for (int i=0;i<I;i++){
        float fi = fp[i];
        #pragma unroll
        for (int j=0;j<J;j++) d += fi*e[j]*w[(i*J+j)*K+k];
    }
    return d;
}

__global__ void k_out(const float* __restrict__ feat, float* __restrict__ out){
    __shared__ float sW[10648];
    __shared__ float sFt[8][22];
    __shared__ float sC[8][66];
    int tid = threadIdx.x, warp = tid>>5, lane = tid&31;
    for (int p=0;p<8;p++)
        for (int i=tid;i<c_OUT_SZ[p];i+=blockDim.x) sW[c_OUT_OFF[p]+i] = g_w3j[6+p][i];
    int node = blockIdx.x*8 + warp;
    int b = node >> 12, n = node & (NN-1);
    if (lane < 22) sFt[warp][lane] = feat[((size_t)b*NN+n)*22 + lane];
    for (int t=lane; t<66; t+=32) sC[warp][t] = g_ctx[b][n][t];
    __syncthreads();
    if (lane < 22){
        const float* F = sFt[warp];
        const float* C = sC[warp];
        float d;
        if (lane < 9){
            int k = lane;
            d  = path_term<9 ,9 ,9>(F  , C   , C+9 , C+18, g_M[0][0],g_M[0][1],g_M[0][2], sW+c_OUT_OFF[0], k);
            d += path_term<9 ,13,9>(F  , C+27, C+40, C+53, g_M[1][0],g_M[1][1],g_M[1][2], sW+c_OUT_OFF[1], k);
            d += path_term<13,9 ,9>(F+9, C   , C+9 , C+18, g_M[2][0],g_M[2][1],g_M[2][2], sW+c_OUT_OFF[2], k);
            d += path_term<13,13,9>(F+9, C+27, C+40, C+53, g_M[3][0],g_M[3][1],g_M[3][2], sW+c_OUT_OFF[3], k);
        } else {
            int k = lane - 9;
            d  = path_term<9 ,9 ,13>(F  , C   , C+9 , C+18, g_M[4][0],g_M[4][1],g_M[4][2], sW+c_OUT_OFF[4], k);
            d += path_term<9 ,13,13>(F  , C+27, C+40, C+53, g_M[5][0],g_M[5][1],g_M[5][2], sW+c_OUT_OFF[5], k);
            d += path_term<13,9 ,13>(F+9, C   , C+9 , C+18, g_M[6][0],g_M[6][1],g_M[6][2], sW+c_OUT_OFF[6], k);
            d += path_term<13,13,13>(F+9, C+27, C+40, C+53, g_M[7][0],g_M[7][1],g_M[7][2], sW+c_OUT_OFF[7], k);
        }
        out[((size_t)b*NN+n)*22 + lane] = d;
    }
}

// ---------------- launch ----------------
extern "C" void kernel_launch(void* const* d_in, const int* in_sizes, int n_in,
                              void* d_out, int out_size){
    const float* feat      = (const float*)d_in[0];
    const float* sh_lr     = (const float*)d_in[1];
    const float* log_s     = (const float*)d_in[2];
    const float* pos_w     = (const float*)d_in[3];
    const float* pos_b     = (const float*)d_in[4];
    const float* w_lin_in  = (const float*)d_in[5];
    const float* w_val     = (const float*)d_in[6];
    const float* w_out     = (const float*)d_in[7];
    const float* w_lin_out = (const float*)d_in[8];
    float* out = (float*)d_out;

    k_init_w3j<<<14,128>>>();
    k_init_small<<<1,32>>>(w_lin_in, w_val, w_out, w_lin_out);
    k_prep<<<(NB*NN)/8, 256>>>(feat, sh_lr, log_s, pos_w, pos_b);
    dim3 g(NN/256, KSPLIT, NB);
    k_flash2<<<g, 256>>>();
    k_rsum<<<(NB*NN)/256, 256>>>();
    k_rctx<<<(NB*NN*66 + 255)/256, 256>>>();
    k_out<<<(NB*NN)/8, 256>>>(feat, out);
}

// round 3
// speedup vs baseline: 1.8509x; 1.3313x over previous
#include <cuda_runtime.h>
#include <cuda_bf16.h>
#include <math.h>

#define NB 4
#define NN 4096
#define CCH 8
#define KSPLIT 8
#define KCH 64

typedef unsigned long long ull;

__device__ __forceinline__ void fma2(ull& d, ull a, ull b){
    asm("fma.rn.f32x2 %0, %1, %2, %0;" : "+l"(d) : "l"(a), "l"(b));
}
__device__ __forceinline__ ull add2(ull a, ull b){
    ull d; asm("add.rn.f32x2 %0, %1, %2;" : "=l"(d) : "l"(a), "l"(b)); return d;
}

// ---------------- device global scratch ----------------
__device__ float g_w3j[14][2197];
__device__ float g_M[8][3];
__device__ float g_pb[NN];
__device__ float g_qk[NB][NN][24];            // 22 used, padded
__device__ float g_rv[NB][NN][68];            // 66 used, padded
__device__ float g_ctx[NB][NN][68];           // 66 used
__device__ float g_part[KSPLIT][NB][NN][68];  // 66 acc + ssum at [66]
__device__ float g_inv[NB*NN];

__constant__ int c_VAL_L[6][3] = {{4,0,4},{4,2,4},{6,2,4},{4,2,6},{6,0,6},{6,2,6}};
__constant__ int c_OUT_L[8][3] = {{4,4,4},{4,6,4},{6,4,4},{6,6,4},{4,4,6},{4,6,6},{6,4,6},{6,6,6}};
__constant__ int c_OUT_OFF[8] = {0,729,1782,2835,4356,5409,6930,8451};
__constant__ int c_VAL_OFF[6] = {0,81,486,1071,1656,1825};
__constant__ int c_VAL_SZ[6]  = {81,405,585,585,169,845};
__constant__ int c_OUT_SZ[8]  = {729,1053,1053,1521,1053,1521,1521,2197};

// ---------------- init: Wigner 3j (fp64, sparse 8-term transform) ----------------
__device__ double d_cg(int l1,int l2,int l3,int m1,int m2,int m3,const double* F){
    if (m1+m2 != m3) return 0.0;
    double pref = sqrt((2.0*l3+1.0)*F[l3+l1-l2]*F[l3-l1+l2]*F[l1+l2-l3]/F[l1+l2+l3+1]);
    pref *= sqrt(F[l3+m3]*F[l3-m3]*F[l1-m1]*F[l1+m1]*F[l2-m2]*F[l2+m2]);
    double s = 0.0;
    for (int k = 0; k <= l1+l2-l3; k++){
        int d0=k, d1=l1+l2-l3-k, d2=l1-m1-k, d3=l2+m2-k, d4=l3-l2+m1+k, d5=l3-l1-m2+k;
        if (d0<0||d1<0||d2<0||d3<0||d4<0||d5<0) continue;
        double den = F[d0]*F[d1]*F[d2]*F[d3]*F[d4]*F[d5];
        s += ((k&1)? -1.0:1.0)/den;
    }
    return pref*s;
}

__device__ void build_q(int l, double2* q){
    int L = 2*l+1;
    for (int i=0;i<L*L;i++) q[i] = make_double2(0.0,0.0);
    double rs2 = 1.0/sqrt(2.0);
    for (int m=-l;m<0;m++){
        q[(l+m)*L + (l-m)] = make_double2(rs2, 0.0);
        q[(l+m)*L + (l+m)] = make_double2(0.0, -rs2);
    }
    q[l*L+l] = make_double2(1.0,0.0);
    for (int m=1;m<=l;m++){
        double sg = (m&1)? -1.0 : 1.0;
        q[(l+m)*L + (l+m)] = make_double2(sg*rs2, 0.0);
        q[(l+m)*L + (l-m)] = make_double2(0.0, sg*rs2);
    }
    double ph = (l % 4 == 0) ? 1.0 : -1.0;
    for (int i=0;i<L*L;i++){ q[i].x *= ph; q[i].y *= ph; }
}

__global__ void k_init_w3j(){
    int t = blockIdx.x;
    int l1,l2,l3;
    if (t<6){ l1=c_VAL_L[t][0]; l2=c_VAL_L[t][1]; l3=c_VAL_L[t][2]; }
    else    { l1=c_OUT_L[t-6][0]; l2=c_OUT_L[t-6][1]; l3=c_OUT_L[t-6][2]; }
    int I=2*l1+1, J=2*l2+1, K=2*l3+1;
    int IJK = I*J*K;
    __shared__ double sF[24];
    __shared__ double sCr[2197];
    __shared__ double2 sQ1[169], sQ2[169], sQ3[169];
    __shared__ double sRed[128];
    __shared__ double sScale;
    int tid = threadIdx.x;
    if (tid < 24){ double r=1.0; for (int i=2;i<=tid;i++) r*= (double)i; sF[tid]=r; }
    if (tid==0) build_q(l1,sQ1);
    if (tid==1) build_q(l2,sQ2);
    if (tid==2) build_q(l3,sQ3);
    __syncthreads();
    // Each Q column j has nonzero rows only in {j, 2l-j}: <=8 terms per output.
    for (int idx=tid; idx<IJK; idx+=blockDim.x){
        int j = idx/(J*K); int r = idx - j*J*K; int l = r/K; int n = r - l*K;
        int ia[2] = {j, 2*l1-j};   int ni = (ia[1]==ia[0])?1:2;
        int kb[2] = {l, 2*l2-l};   int nk = (kb[1]==kb[0])?1:2;
        int mc[2] = {n, 2*l3-n};   int nm = (mc[1]==mc[0])?1:2;
        double acc = 0.0;
        for (int a=0;a<ni;a++){
            int i = ia[a];
            double2 q1 = sQ1[i*I+j];
            if (q1.x==0.0 && q1.y==0.0) continue;
            for (int bq=0;bq<nk;bq++){
                int k2 = kb[bq];
                double2 q2 = sQ2[k2*J+l];
                if (q2.x==0.0 && q2.y==0.0) continue;
                double px = q1.x*q2.x - q1.y*q2.y;
                double py = q1.x*q2.y + q1.y*q2.x;
                for (int cq=0;cq<nm;cq++){
                    int m = mc[cq];
                    double2 q3 = sQ3[m*K+n];
                    if (q3.x==0.0 && q3.y==0.0) continue;
                    double cg = d_cg(l1,l2,l3, i-l1, k2-l2, m-l3, sF);
                    if (cg==0.0) continue;
                    acc += (px*q3.x + py*q3.y)*cg;
                }
            }
        }
        sCr[idx] = acc;
    }
    __syncthreads();
    double ss = 0.0;
    for (int idx=tid; idx<IJK; idx+=blockDim.x) ss += sCr[idx]*sCr[idx];
    sRed[tid] = ss;
    __syncthreads();
    for (int s=64;s>0;s>>=1){ if (tid<s) sRed[tid]+=sRed[tid+s]; __syncthreads(); }
    if (tid==0){
        double nrm = sqrt(sRed[0]);
        double sc = (t<6)? sqrt((double)K/(3.0*CCH)) : sqrt((double)K/(4.0*CCH*CCH));
        sScale = sc/nrm;
    }
    __syncthreads();
    for (int idx=tid; idx<IJK; idx+=blockDim.x)
        g_w3j[t][idx] = (float)(sCr[idx]*sScale);
}

// ---------------- init: M[p][qq] ----------------
__global__ void k_init_small(const float* __restrict__ w_lin_in, const float* __restrict__ w_val,
                             const float* __restrict__ w_out, const float* __restrict__ w_lin_out){
    int tid = threadIdx.x;
    if (tid < 24){
        int p = tid/3, qq = tid - p*3;
        int l1o = c_OUT_L[p][0], l2o = c_OUT_L[p][1], l3o = c_OUT_L[p][2];
        const float* wli_p = w_lin_in + (l1o==4 ? 0 : 8);
        const float* wlo   = w_lin_out + (l3o==4 ? 0 : 8);
        int q = (l2o==4 ? 0 : 3) + qq;
        const float* wli_q = w_lin_in + (c_VAL_L[q][0]==4 ? 0 : 8);
        float m = 0.f;
        for (int v=0; v<8; v++){
            float cpv = 0.f;
            for (int u=0; u<8; u++){
                float wu = wli_p[u];
                const float* wo = w_out + ((p*8+u)*8+v)*8;
                for (int w=0; w<8; w++) cpv += wu * wo[w] * wlo[w];
            }
            float aqv = 0.f;
            for (int u=0; u<8; u++) aqv += wli_q[u]*w_val[(q*8+u)*8+v];
            m += cpv*aqv;
        }
        g_M[p][qq] = m * 0.35355339059327373f;
    }
}

// ---------------- prep ----------------
__global__ void k_prep(const float* __restrict__ feat, const float* __restrict__ sh_lr,
                       const float* __restrict__ log_s, const float* __restrict__ pos_w,
                       const float* __restrict__ pos_b){
    __shared__ float sW[2670];
    __shared__ float sFt[8][22];
    __shared__ float sY[8][6];
    int tid = threadIdx.x, warp = tid>>5, lane = tid&31;
    for (int p=0;p<6;p++)
        for (int i=tid;i<c_VAL_SZ[p];i+=blockDim.x) sW[c_VAL_OFF[p]+i] = g_w3j[p][i];
    int node = blockIdx.x*8 + warp;
    int b = node >> 12, n = node & (NN-1);
    const float* f = feat + ((size_t)b*NN + n)*22;
    if (lane < 22) sFt[warp][lane] = f[lane];
    if (lane < 6)  sY[warp][lane]  = sh_lr[n*6+lane];
    __syncthreads();
    float n4=0.f, n6=0.f;
    #pragma unroll
    for (int d=0; d<9; d++){ float v=sFt[warp][d]; n4 += v*v; }
    #pragma unroll
    for (int d=9; d<22; d++){ float v=sFt[warp][d]; n6 += v*v; }
    float s4 = __expf(log_s[0]), s6 = __expf(log_s[1]);
    float r4 = sqrtf(s4)/fmaxf(sqrtf(n4), 1e-12f);
    float r6 = sqrtf(s6)/fmaxf(sqrtf(n6), 1e-12f);
    float* qk = &g_qk[b][n][0];
    if (lane < 9)        qk[lane] = sFt[warp][lane]*r4;
    else if (lane < 22)  qk[lane] = sFt[warp][lane]*r6;
    else if (lane < 24)  qk[lane] = 0.f;
    if (b==0 && lane==0){
        float pb = pos_b[0];
        for (int j=0;j<6;j++) pb += sY[warp][j]*pos_w[j];
        g_pb[n] = pb;
    }
    float* rv = &g_rv[b][n][0];
    for (int t=lane; t<68; t+=32){
        if (t >= 66){ rv[t] = 0.f; continue; }
        int p,k;
        if (t < 27){ p = t/9; k = t - p*9; } else { int u=t-27; p = 3 + u/13; k = u - (p-3)*13; }
        int l1 = c_VAL_L[p][0], l2 = c_VAL_L[p][1];
        int I = 2*l1+1, J = 2*l2+1, K = 2*c_VAL_L[p][2]+1;
        int foff = (l1==4)? 0 : 9;
        const float* w = sW + c_VAL_OFF[p];
        float r = 0.f;
        if (J == 1){
            float y0 = sY[warp][0];
            for (int i=0;i<I;i++) r += sFt[warp][foff+i]*y0*w[i*K+k];
        } else {
            for (int i=0;i<I;i++){
                float fi = sFt[warp][foff+i];
                #pragma unroll
                for (int j=0;j<5;j++) r += fi*sY[warp][1+j]*w[(i*5+j)*K+k];
            }
        }
        rv[t] = r;
    }
}

// ---------------- flash attention v3: 4 independent score chains, f32x2 hadd ----------------
__global__ void __launch_bounds__(256,2) k_flash2(){
    __shared__ float sK[KCH][24];
    __shared__ float sV[KCH][68];
    __shared__ float sPB[KCH];
    int b = blockIdx.z, split = blockIdx.y;
    int tid = threadIdx.x;
    int n = blockIdx.x*256 + tid;

    ull qr[11];
    {
        const ull* qp = (const ull*)&g_qk[b][n][0];
        #pragma unroll
        for (int i=0;i<11;i++) qr[i]=qp[i];
    }
    ull acc[33];
    #pragma unroll
    for (int i=0;i<33;i++) acc[i]=0ull;
    float ssum = 0.f;

    int ks0 = split*(NN/KSPLIT);
    for (int c=0; c<(NN/KSPLIT)/KCH; c++){
        int kbase = ks0 + c*KCH;
        {
            const float4* gk = (const float4*)&g_qk[b][kbase][0];
            float4* sk4 = (float4*)&sK[0][0];
            #pragma unroll 2
            for (int i=tid; i<KCH*6; i+=256) sk4[i]=gk[i];
            const float4* gv = (const float4*)&g_rv[b][kbase][0];
            float4* sv4 = (float4*)&sV[0][0];
            #pragma unroll 5
            for (int i=tid; i<KCH*17; i+=256) sv4[i]=gv[i];
            if (tid<KCH) sPB[tid]=g_pb[kbase+tid];
        }
        __syncthreads();
        #pragma unroll 2
        for (int kk=0; kk<KCH; kk++){
            // score: 22-dim dot, FOUR independent f32x2 chains (depth <=3)
            const ulonglong2* kr2 = (const ulonglong2*)&sK[kk][0];
            ulonglong2 t0 = kr2[0], t1 = kr2[1], t2 = kr2[2], t3 = kr2[3], t4 = kr2[4];
            ull k10 = ((const ull*)&sK[kk][0])[10];
            ull sa=0ull, sb=0ull, sc2=0ull, sd=0ull;
            fma2(sa, qr[0], t0.x); fma2(sb, qr[1], t0.y);
            fma2(sc2, qr[2], t1.x); fma2(sd, qr[3], t1.y);
            fma2(sa, qr[4], t2.x); fma2(sb, qr[5], t2.y);
            fma2(sc2, qr[6], t3.x); fma2(sd, qr[7], t3.y);
            fma2(sa, qr[8], t4.x); fma2(sb, qr[9], t4.y);
            fma2(sc2, qr[10], k10);
            ull sab = add2(sa, sb);
            ull scd = add2(sc2, sd);
            ull st  = add2(sab, scd);
            float x0,x1;
            asm("mov.b64 {%0,%1}, %2;" : "=f"(x0), "=f"(x1) : "l"(st));
            float s = x0 + x1 + sPB[kk];
            float p = __expf(s);
            ssum += p;
            ull pp; asm("mov.b64 %0, {%1,%1};" : "=l"(pp) : "f"(p));
            const ulonglong2* vr2 = (const ulonglong2*)&sV[kk][0];
            #pragma unroll
            for (int i=0;i<16;i++){
                ulonglong2 t = vr2[i];
                fma2(acc[2*i],   pp, t.x);
                fma2(acc[2*i+1], pp, t.y);
            }
            {
                ull v32 = ((const ull*)&sV[kk][0])[32];
                fma2(acc[32], pp, v32);
            }
        }
        __syncthreads();
    }
    ull* po = (ull*)&g_part[split][b][n][0];
    #pragma unroll
    for (int i=0;i<33;i++) po[i]=acc[i];
    ((float*)po)[66] = ssum;
}

// ---------------- combine K-split partials ----------------
__global__ void k_rsum(){
    int id = blockIdx.x*256 + threadIdx.x;
    int b = id>>12, n = id&(NN-1);
    float s=0.f;
    #pragma unroll
    for (int sp=0; sp<KSPLIT; sp++) s += g_part[sp][b][n][66];
    g_inv[id] = 1.f/s;
}

__global__ void k_rctx(){
    int id = blockIdx.x*256 + threadIdx.x;
    if (id >= NB*NN*66) return;
    int node = id/66; int d = id - node*66;
    int b = node>>12, n = node&(NN-1);
    float s=0.f;
    #pragma unroll
    for (int sp=0; sp<KSPLIT; sp++) s += g_part[sp][b][n][d];
    g_ctx[b][n][d] = s*g_inv[node];
}

// ---------------- out ----------------
template<int I,int J,int K>
__device__ __forceinline__ float path_term(const float* fp, const float* c0, const float* c1, const float* c2,
                                           float m0, float m1, float m2, const float* w, int k){
    float e[J];
    #pragma unroll
    for (int j=0;j<J;j++) e[j] = m0*c0[j] + m1*c1[j] + m2*c2[j];
    float d = 0.f;
    for (int i=0;i<I;i++){
        float fi = fp[i];
        #pragma unroll
        for (int j=0;j<J;j++) d += fi*e[j]*w[(i*J+j)*K+k];
    }
    return d;
}

__global__ void k_out(const float* __restrict__ feat, float* __restrict__ out){
    __shared__ float sW[10648];
    __shared__ float sFt[8][22];
    __shared__ float sC[8][66];
    int tid = threadIdx.x, warp = tid>>5, lane = tid&31;
    for (int p=0;p<8;p++)
        for (int i=tid;i<c_OUT_SZ[p];i+=blockDim.x) sW[c_OUT_OFF[p]+i] = g_w3j[6+p][i];
    int node = blockIdx.x*8 + warp;
    int b = node >> 12, n = node & (NN-1);
    if (lane < 22) sFt[warp][lane] = feat[((size_t)b*NN+n)*22 + lane];
    for (int t=lane; t<66; t+=32) sC[warp][t] = g_ctx[b][n][t];
    __syncthreads();
    if (lane < 22){
        const float* F = sFt[warp];
        const float* C = sC[warp];
        float d;
        if (lane < 9){
            int k = lane;
            d  = path_term<9 ,9 ,9>(F  , C   , C+9 , C+18, g_M[0][0],g_M[0][1],g_M[0][2], sW+c_OUT_OFF[0], k);
            d += path_term<9 ,13,9>(F  , C+27, C+40, C+53, g_M[1][0],g_M[1][1],g_M[1][2], sW+c_OUT_OFF[1], k);
            d += path_term<13,9 ,9>(F+9, C   , C+9 , C+18, g_M[2][0],g_M[2][1],g_M[2][2], sW+c_OUT_OFF[2], k);
            d += path_term<13,13,9>(F+9, C+27, C+40, C+53, g_M[3][0],g_M[3][1],g_M[3][2], sW+c_OUT_OFF[3], k);
        } else {
            int k = lane - 9;
            d  = path_term<9 ,9 ,13>(F  , C   , C+9 , C+18, g_M[4][0],g_M[4][1],g_M[4][2], sW+c_OUT_OFF[4], k);
            d += path_term<9 ,13,13>(F  , C+27, C+40, C+53, g_M[5][0],g_M[5][1],g_M[5][2], sW+c_OUT_OFF[5], k);
            d += path_term<13,9 ,13>(F+9, C   , C+9 , C+18, g_M[6][0],g_M[6][1],g_M[6][2], sW+c_OUT_OFF[6], k);
            d += path_term<13,13,13>(F+9, C+27, C+40, C+53, g_M[7][0],g_M[7][1],g_M[7][2], sW+c_OUT_OFF[7], k);
        }
        out[((size_t)b*NN+n)*22 + lane] = d;
    }
}

// ---------------- launch ----------------
extern "C" void kernel_launch(void* const* d_in, const int* in_sizes, int n_in,
                              void* d_out, int out_size){
    const float* feat      = (const float*)d_in[0];
    const float* sh_lr     = (const float*)d_in[1];
    const float* log_s     = (const float*)d_in[2];
    const float* pos_w     = (const float*)d_in[3];
    const float* pos_b     = (const float*)d_in[4];
    const float* w_lin_in  = (const float*)d_in[5];
    const float* w_val     = (const float*)d_in[6];
    const float* w_out     = (const float*)d_in[7];
    const float* w_lin_out = (const float*)d_in[8];
    float* out = (float*)d_out;

    k_init_w3j<<<14,128>>>();
    k_init_small<<<1,32>>>(w_lin_in, w_val, w_out, w_lin_out);
    k_prep<<<(NB*NN)/8, 256>>>(feat, sh_lr, log_s, pos_w, pos_b);
    dim3 g(NN/256, KSPLIT, NB);
    k_flash2<<<g, 256>>>();
    k_rsum<<<(NB*NN)/256, 256>>>();
    k_rctx<<<(NB*NN*66 + 255)/256, 256>>>();
    k_out<<<(NB*NN)/8, 256>>>(feat, out);
}

// round 4
// speedup vs baseline: 2.6133x; 1.4119x over previous
#include <cuda_runtime.h>
#include <cuda_bf16.h>
#include <math.h>

#define NB 4
#define NN 4096
#define CCH 8
#define KSPLIT 8
#define KCH 64
#define WCHUNK 64

typedef unsigned long long ull;

__device__ __forceinline__ void fma2(ull& d, ull a, ull b){
    asm("fma.rn.f32x2 %0, %1, %2, %0;" : "+l"(d) : "l"(a), "l"(b));
}
__device__ __forceinline__ ull add2(ull a, ull b){
    ull d; asm("add.rn.f32x2 %0, %1, %2;" : "=l"(d) : "l"(a), "l"(b)); return d;
}

// ---------------- device global scratch ----------------
__device__ float g_w3j[14][2197];
__device__ double g_psum[14][WCHUNK];
__device__ float g_M[8][3];
__device__ float g_pb[NN];
__device__ float g_qk[NB][NN][24];            // 22 used, padded
__device__ float g_rv[NB][NN][68];            // 66 used, padded
__device__ float g_ctx[NB][NN][68];           // 66 used
__device__ float g_part[KSPLIT][NB][NN][68];  // 66 acc + ssum at [66]
__device__ float g_inv[NB*NN];

__constant__ int c_VAL_L[6][3] = {{4,0,4},{4,2,4},{6,2,4},{4,2,6},{6,0,6},{6,2,6}};
__constant__ int c_OUT_L[8][3] = {{4,4,4},{4,6,4},{6,4,4},{6,6,4},{4,4,6},{4,6,6},{6,4,6},{6,6,6}};
__constant__ int c_OUT_OFF[8] = {0,729,1782,2835,4356,5409,6930,8451};
__constant__ int c_VAL_OFF[6] = {0,81,486,1071,1656,1825};
__constant__ int c_VAL_SZ[6]  = {81,405,585,585,169,845};
__constant__ int c_OUT_SZ[8]  = {729,1053,1053,1521,1053,1521,1521,2197};

// ---------------- init: Wigner 3j (fp64, sparse transform, chip-wide spread) ----------------
__device__ double d_cg(int l1,int l2,int l3,int m1,int m2,int m3,const double* F){
    if (m1+m2 != m3) return 0.0;
    double pA = (2.0*l3+1.0)*F[l3+l1-l2]*F[l3-l1+l2]*F[l1+l2-l3]/F[l1+l2+l3+1];
    double pB = F[l3+m3]*F[l3-m3]*F[l1-m1]*F[l1+m1]*F[l2-m2]*F[l2+m2];
    double pref = sqrt(pA*pB);                       // single fp64 sqrt
    double s = 0.0;
    for (int k = 0; k <= l1+l2-l3; k++){
        int d0=k, d1=l1+l2-l3-k, d2=l1-m1-k, d3=l2+m2-k, d4=l3-l2+m1+k, d5=l3-l1-m2+k;
        if (d0<0||d1<0||d2<0||d3<0||d4<0||d5<0) continue;
        double den = F[d0]*F[d1]*F[d2]*F[d3]*F[d4]*F[d5];
        s += ((k&1)? -1.0:1.0)/den;
    }
    return pref*s;
}

__device__ void build_q(int l, double2* q){
    int L = 2*l+1;
    for (int i=0;i<L*L;i++) q[i] = make_double2(0.0,0.0);
    double rs2 = 1.0/sqrt(2.0);
    for (int m=-l;m<0;m++){
        q[(l+m)*L + (l-m)] = make_double2(rs2, 0.0);
        q[(l+m)*L + (l+m)] = make_double2(0.0, -rs2);
    }
    q[l*L+l] = make_double2(1.0,0.0);
    for (int m=1;m<=l;m++){
        double sg = (m&1)? -1.0 : 1.0;
        q[(l+m)*L + (l+m)] = make_double2(sg*rs2, 0.0);
        q[(l+m)*L + (l-m)] = make_double2(0.0, sg*rs2);
    }
    double ph = (l % 4 == 0) ? 1.0 : -1.0;
    for (int i=0;i<L*L;i++){ q[i].x *= ph; q[i].y *= ph; }
}

// Phase A: unnormalized values + per-chunk partial sum of squares.
// grid = (14, WCHUNK), block = 128.
__global__ void k_init_w3j_a(){
    int t = blockIdx.x, chunk = blockIdx.y;
    int l1,l2,l3;
    if (t<6){ l1=c_VAL_L[t][0]; l2=c_VAL_L[t][1]; l3=c_VAL_L[t][2]; }
    else    { l1=c_OUT_L[t-6][0]; l2=c_OUT_L[t-6][1]; l3=c_OUT_L[t-6][2]; }
    int I=2*l1+1, J=2*l2+1, K=2*l3+1;
    int IJK = I*J*K;
    int len = (IJK + WCHUNK - 1)/WCHUNK;
    int lo = chunk*len, hi = min(lo+len, IJK);
    __shared__ double sF[24];
    __shared__ double2 sQ1[169], sQ2[169], sQ3[169];
    __shared__ double sRed[128];
    int tid = threadIdx.x;
    if (tid < 24){ double r=1.0; for (int i=2;i<=tid;i++) r*= (double)i; sF[tid]=r; }
    if (tid==0) build_q(l1,sQ1);
    if (tid==1) build_q(l2,sQ2);
    if (tid==2) build_q(l3,sQ3);
    __syncthreads();
    double ss = 0.0;
    for (int idx=lo+tid; idx<hi; idx+=blockDim.x){
        int j = idx/(J*K); int r = idx - j*J*K; int l = r/K; int n = r - l*K;
        int ia[2] = {j, 2*l1-j};   int ni = (ia[1]==ia[0])?1:2;
        int kb[2] = {l, 2*l2-l};   int nk = (kb[1]==kb[0])?1:2;
        int mc[2] = {n, 2*l3-n};   int nm = (mc[1]==mc[0])?1:2;
        double acc = 0.0;
        for (int a=0;a<ni;a++){
            int i = ia[a];
            double2 q1 = sQ1[i*I+j];
            if (q1.x==0.0 && q1.y==0.0) continue;
            for (int bq=0;bq<nk;bq++){
                int k2 = kb[bq];
                double2 q2 = sQ2[k2*J+l];
                if (q2.x==0.0 && q2.y==0.0) continue;
                double px = q1.x*q2.x - q1.y*q2.y;
                double py = q1.x*q2.y + q1.y*q2.x;
                for (int cq=0;cq<nm;cq++){
                    int m = mc[cq];
                    double2 q3 = sQ3[m*K+n];
                    if (q3.x==0.0 && q3.y==0.0) continue;
                    double cg = d_cg(l1,l2,l3, i-l1, k2-l2, m-l3, sF);
                    if (cg==0.0) continue;
                    acc += (px*q3.x + py*q3.y)*cg;
                }
            }
        }
        g_w3j[t][idx] = (float)acc;
        ss += acc*acc;
    }
    sRed[tid] = ss;
    __syncthreads();
    for (int s=64;s>0;s>>=1){ if (tid<s) sRed[tid]+=sRed[tid+s]; __syncthreads(); }
    if (tid==0) g_psum[t][chunk] = sRed[0];
}

// Phase B: deterministic norm + rescale. grid = 14, block = 128.
__global__ void k_init_w3j_b(){
    int t = blockIdx.x;
    int l3 = (t<6)? c_VAL_L[t][2] : c_OUT_L[t-6][2];
    int K = 2*l3+1;
    int IJK;
    if (t<6){ int l1=c_VAL_L[t][0], l2=c_VAL_L[t][1]; IJK=(2*l1+1)*(2*l2+1)*K; }
    else    { int l1=c_OUT_L[t-6][0], l2=c_OUT_L[t-6][1]; IJK=(2*l1+1)*(2*l2+1)*K; }
    __shared__ float sScale;
    if (threadIdx.x==0){
        double nrm2 = 0.0;
        for (int c=0;c<WCHUNK;c++) nrm2 += g_psum[t][c];   // fixed order: deterministic
        double sc = (t<6)? sqrt((double)K/(3.0*CCH)) : sqrt((double)K/(4.0*CCH*CCH));
        sScale = (float)(sc/sqrt(nrm2));
    }
    __syncthreads();
    float s = sScale;
    for (int idx=threadIdx.x; idx<IJK; idx+=blockDim.x)
        g_w3j[t][idx] *= s;
}

// ---------------- init: M[p][qq] ----------------
__global__ void k_init_small(const float* __restrict__ w_lin_in, const float* __restrict__ w_val,
                             const float* __restrict__ w_out, const float* __restrict__ w_lin_out){
    int tid = threadIdx.x;
    if (tid < 24){
        int p = tid/3, qq = tid - p*3;
        int l1o = c_OUT_L[p][0], l2o = c_OUT_L[p][1], l3o = c_OUT_L[p][2];
        const float* wli_p = w_lin_in + (l1o==4 ? 0 : 8);
        const float* wlo   = w_lin_out + (l3o==4 ? 0 : 8);
        int q = (l2o==4 ? 0 : 3) + qq;
        const float* wli_q = w_lin_in + (c_VAL_L[q][0]==4 ? 0 : 8);
        float m = 0.f;
        for (int v=0; v<8; v++){
            float cpv = 0.f;
            for (int u=0; u<8; u++){
                float wu = wli_p[u];
                const float* wo = w_out + ((p*8+u)*8+v)*8;
                for (int w=0; w<8; w++) cpv += wu * wo[w] * wlo[w];
            }
            float aqv = 0.f;
            for (int u=0; u<8; u++) aqv += wli_q[u]*w_val[(q*8+u)*8+v];
            m += cpv*aqv;
        }
        g_M[p][qq] = m * 0.35355339059327373f;
    }
}

// ---------------- prep ----------------
__global__ void k_prep(const float* __restrict__ feat, const float* __restrict__ sh_lr,
                       const float* __restrict__ log_s, const float* __restrict__ pos_w,
                       const float* __restrict__ pos_b){
    __shared__ float sW[2670];
    __shared__ float sFt[8][22];
    __shared__ float sY[8][6];
    int tid = threadIdx.x, warp = tid>>5, lane = tid&31;
    for (int p=0;p<6;p++)
        for (int i=tid;i<c_VAL_SZ[p];i+=blockDim.x) sW[c_VAL_OFF[p]+i] = g_w3j[p][i];
    int node = blockIdx.x*8 + warp;
    int b = node >> 12, n = node & (NN-1);
    const float* f = feat + ((size_t)b*NN + n)*22;
    if (lane < 22) sFt[warp][lane] = f[lane];
    if (lane < 6)  sY[warp][lane]  = sh_lr[n*6+lane];
    __syncthreads();
    float n4=0.f, n6=0.f;
    #pragma unroll
    for (int d=0; d<9; d++){ float v=sFt[warp][d]; n4 += v*v; }
    #pragma unroll
    for (int d=9; d<22; d++){ float v=sFt[warp][d]; n6 += v*v; }
    float s4 = __expf(log_s[0]), s6 = __expf(log_s[1]);
    float r4 = sqrtf(s4)/fmaxf(sqrtf(n4), 1e-12f);
    float r6 = sqrtf(s6)/fmaxf(sqrtf(n6), 1e-12f);
    float* qk = &g_qk[b][n][0];
    if (lane < 9)        qk[lane] = sFt[warp][lane]*r4;
    else if (lane < 22)  qk[lane] = sFt[warp][lane]*r6;
    else if (lane < 24)  qk[lane] = 0.f;
    if (b==0 && lane==0){
        float pb = pos_b[0];
        for (int j=0;j<6;j++) pb += sY[warp][j]*pos_w[j];
        g_pb[n] = pb;
    }
    float* rv = &g_rv[b][n][0];
    for (int t=lane; t<68; t+=32){
        if (t >= 66){ rv[t] = 0.f; continue; }
        int p,k;
        if (t < 27){ p = t/9; k = t - p*9; } else { int u=t-27; p = 3 + u/13; k = u - (p-3)*13; }
        int l1 = c_VAL_L[p][0], l2 = c_VAL_L[p][1];
        int I = 2*l1+1, J = 2*l2+1, K = 2*c_VAL_L[p][2]+1;
        int foff = (l1==4)? 0 : 9;
        const float* w = sW + c_VAL_OFF[p];
        float r = 0.f;
        if (J == 1){
            float y0 = sY[warp][0];
            for (int i=0;i<I;i++) r += sFt[warp][foff+i]*y0*w[i*K+k];
        } else {
            for (int i=0;i<I;i++){
                float fi = sFt[warp][foff+i];
                #pragma unroll
                for (int j=0;j<5;j++) r += fi*sY[warp][1+j]*w[(i*5+j)*K+k];
            }
        }
        rv[t] = r;
    }
}

// ---------------- flash attention: 4 independent score chains, f32x2 ----------------
__global__ void __launch_bounds__(256,2) k_flash2(){
    __shared__ float sK[KCH][24];
    __shared__ float sV[KCH][68];
    __shared__ float sPB[KCH];
    int b = blockIdx.z, split = blockIdx.y;
    int tid = threadIdx.x;
    int n = blockIdx.x*256 + tid;

    ull qr[11];
    {
        const ull* qp = (const ull*)&g_qk[b][n][0];
        #pragma unroll
        for (int i=0;i<11;i++) qr[i]=qp[i];
    }
    ull acc[33];
    #pragma unroll
    for (int i=0;i<33;i++) acc[i]=0ull;
    float ssum = 0.f;

    int ks0 = split*(NN/KSPLIT);
    for (int c=0; c<(NN/KSPLIT)/KCH; c++){
        int kbase = ks0 + c*KCH;
        {
            const float4* gk = (const float4*)&g_qk[b][kbase][0];
            float4* sk4 = (float4*)&sK[0][0];
            #pragma unroll 2
            for (int i=tid; i<KCH*6; i+=256) sk4[i]=gk[i];
            const float4* gv = (const float4*)&g_rv[b][kbase][0];
            float4* sv4 = (float4*)&sV[0][0];
            #pragma unroll 5
            for (int i=tid; i<KCH*17; i+=256) sv4[i]=gv[i];
            if (tid<KCH) sPB[tid]=g_pb[kbase+tid];
        }
        __syncthreads();
        #pragma unroll 2
        for (int kk=0; kk<KCH; kk++){
            const ulonglong2* kr2 = (const ulonglong2*)&sK[kk][0];
            ulonglong2 t0 = kr2[0], t1 = kr2[1], t2 = kr2[2], t3 = kr2[3], t4 = kr2[4];
            ull k10 = ((const ull*)&sK[kk][0])[10];
            ull sa=0ull, sb=0ull, sc2=0ull, sd=0ull;
            fma2(sa, qr[0], t0.x); fma2(sb, qr[1], t0.y);
            fma2(sc2, qr[2], t1.x); fma2(sd, qr[3], t1.y);
            fma2(sa, qr[4], t2.x); fma2(sb, qr[5], t2.y);
            fma2(sc2, qr[6], t3.x); fma2(sd, qr[7], t3.y);
            fma2(sa, qr[8], t4.x); fma2(sb, qr[9], t4.y);
            fma2(sc2, qr[10], k10);
            ull sab = add2(sa, sb);
            ull scd = add2(sc2, sd);
            ull st  = add2(sab, scd);
            float x0,x1;
            asm("mov.b64 {%0,%1}, %2;" : "=f"(x0), "=f"(x1) : "l"(st));
            float s = x0 + x1 + sPB[kk];
            float p = __expf(s);
            ssum += p;
            ull pp; asm("mov.b64 %0, {%1,%1};" : "=l"(pp) : "f"(p));
            const ulonglong2* vr2 = (const ulonglong2*)&sV[kk][0];
            #pragma unroll
            for (int i=0;i<16;i++){
                ulonglong2 t = vr2[i];
                fma2(acc[2*i],   pp, t.x);
                fma2(acc[2*i+1], pp, t.y);
            }
            {
                ull v32 = ((const ull*)&sV[kk][0])[32];
                fma2(acc[32], pp, v32);
            }
        }
        __syncthreads();
    }
    ull* po = (ull*)&g_part[split][b][n][0];
    #pragma unroll
    for (int i=0;i<33;i++) po[i]=acc[i];
    ((float*)po)[66] = ssum;
}

// ---------------- combine K-split partials ----------------
__global__ void k_rsum(){
    int id = blockIdx.x*256 + threadIdx.x;
    int b = id>>12, n = id&(NN-1);
    float s=0.f;
    #pragma unroll
    for (int sp=0; sp<KSPLIT; sp++) s += g_part[sp][b][n][66];
    g_inv[id] = 1.f/s;
}

__global__ void k_rctx(){
    int id = blockIdx.x*256 + threadIdx.x;
    if (id >= NB*NN*66) return;
    int node = id/66; int d = id - node*66;
    int b = node>>12, n = node&(NN-1);
    float s=0.f;
    #pragma unroll
    for (int sp=0; sp<KSPLIT; sp++) s += g_part[sp][b][n][d];
    g_ctx[b][n][d] = s*g_inv[node];
}

// ---------------- out ----------------
template<int I,int J,int K>
__device__ __forceinline__ float path_term(const float* fp, const float* c0, const float* c1, const float* c2,
                                           float m0, float m1, float m2, const float* w, int k){
    float e[J];
    #pragma unroll
    for (int j=0;j<J;j++) e[j] = m0*c0[j] + m1*c1[j] + m2*c2[j];
    float d = 0.f;
    for (int i=0;i<I;i++){
        float fi = fp[i];
        #pragma unroll
        for (int j=0;j<J;j++) d += fi*e[j]*w[(i*J+j)*K+k];
    }
    return d;
}

__global__ void k_out(const float* __restrict__ feat, float* __restrict__ out){
    __shared__ float sW[10648];
    __shared__ float sFt[8][22];
    __shared__ float sC[8][66];
    int tid = threadIdx.x, warp = tid>>5, lane = tid&31;
    for (int p=0;p<8;p++)
        for (int i=tid;i<c_OUT_SZ[p];i+=blockDim.x) sW[c_OUT_OFF[p]+i] = g_w3j[6+p][i];
    int node = blockIdx.x*8 + warp;
    int b = node >> 12, n = node & (NN-1);
    if (lane < 22) sFt[warp][lane] = feat[((size_t)b*NN+n)*22 + lane];
    for (int t=lane; t<66; t+=32) sC[warp][t] = g_ctx[b][n][t];
    __syncthreads();
    if (lane < 22){
        const float* F = sFt[warp];
        const float* C = sC[warp];
        float d;
        if (lane < 9){
            int k = lane;
            d  = path_term<9 ,9 ,9>(F  , C   , C+9 , C+18, g_M[0][0],g_M[0][1],g_M[0][2], sW+c_OUT_OFF[0], k);
            d += path_term<9 ,13,9>(F  , C+27, C+40, C+53, g_M[1][0],g_M[1][1],g_M[1][2], sW+c_OUT_OFF[1], k);
            d += path_term<13,9 ,9>(F+9, C   , C+9 , C+18, g_M[2][0],g_M[2][1],g_M[2][2], sW+c_OUT_OFF[2], k);
            d += path_term<13,13,9>(F+9, C+27, C+40, C+53, g_M[3][0],g_M[3][1],g_M[3][2], sW+c_OUT_OFF[3], k);
        } else {
            int k = lane - 9;
            d  = path_term<9 ,9 ,13>(F  , C   , C+9 , C+18, g_M[4][0],g_M[4][1],g_M[4][2], sW+c_OUT_OFF[4], k);
            d += path_term<9 ,13,13>(F  , C+27, C+40, C+53, g_M[5][0],g_M[5][1],g_M[5][2], sW+c_OUT_OFF[5], k);
            d += path_term<13,9 ,13>(F+9, C   , C+9 , C+18, g_M[6][0],g_M[6][1],g_M[6][2], sW+c_OUT_OFF[6], k);
            d += path_term<13,13,13>(F+9, C+27, C+40, C+53, g_M[7][0],g_M[7][1],g_M[7][2], sW+c_OUT_OFF[7], k);
        }
        out[((size_t)b*NN+n)*22 + lane] = d;
    }
}

// ---------------- launch ----------------
extern "C" void kernel_launch(void* const* d_in, const int* in_sizes, int n_in,
                              void* d_out, int out_size){
    const float* feat      = (const float*)d_in[0];
    const float* sh_lr     = (const float*)d_in[1];
    const float* log_s     = (const float*)d_in[2];
    const float* pos_w     = (const float*)d_in[3];
    const float* pos_b     = (const float*)d_in[4];
    const float* w_lin_in  = (const float*)d_in[5];
    const float* w_val     = (const float*)d_in[6];
    const float* w_out     = (const float*)d_in[7];
    const float* w_lin_out = (const float*)d_in[8];
    float* out = (float*)d_out;

    dim3 gi(14, WCHUNK);
    k_init_w3j_a<<<gi, 128>>>();
    k_init_w3j_b<<<14, 128>>>();
    k_init_small<<<1,32>>>(w_lin_in, w_val, w_out, w_lin_out);
    k_prep<<<(NB*NN)/8, 256>>>(feat, sh_lr, log_s, pos_w, pos_b);
    dim3 g(NN/256, KSPLIT, NB);
    k_flash2<<<g, 256>>>();
    k_rsum<<<(NB*NN)/256, 256>>>();
    k_rctx<<<(NB*NN*66 + 255)/256, 256>>>();
    k_out<<<(NB*NN)/8, 256>>>(feat, out);
}

// round 7
// speedup vs baseline: 3.6985x; 1.4153x over previous
#include <cuda_runtime.h>
#include <cuda_bf16.h>
#include <math.h>
#include <stdint.h>

#define NB 4
#define NN 4096
#define CCH 8
#define WCHUNK 64

typedef unsigned long long ull;

__device__ __forceinline__ void fma2(ull& d, ull a, ull b){
    asm("fma.rn.f32x2 %0, %1, %2, %0;" : "+l"(d) : "l"(a), "l"(b));
}
__device__ __forceinline__ ull add2(ull a, ull b){
    ull d; asm("add.rn.f32x2 %0, %1, %2;" : "=l"(d) : "l"(a), "l"(b)); return d;
}
__device__ __forceinline__ uint32_t s2u(const void* p){
    uint32_t a;
    asm("{ .reg .u64 t; cvta.to.shared.u64 t, %1; cvt.u32.u64 %0, t; }" : "=r"(a) : "l"(p));
    return a;
}
__device__ __forceinline__ void cpasync16(uint32_t dst, const void* src){
    asm volatile("cp.async.cg.shared.global [%0], [%1], 16;" :: "r"(dst), "l"(src));
}
#define CP_COMMIT() asm volatile("cp.async.commit_group;" ::: "memory")

__device__ __forceinline__ void ldmx4(uint32_t& r0, uint32_t& r1, uint32_t& r2, uint32_t& r3, uint32_t a){
    asm volatile("ldmatrix.sync.aligned.m8n8.x4.shared.b16 {%0,%1,%2,%3}, [%4];"
        : "=r"(r0), "=r"(r1), "=r"(r2), "=r"(r3) : "r"(a));
}
__device__ __forceinline__ void ldmx2(uint32_t& r0, uint32_t& r1, uint32_t a){
    asm volatile("ldmatrix.sync.aligned.m8n8.x2.shared.b16 {%0,%1}, [%2];"
        : "=r"(r0), "=r"(r1) : "r"(a));
}
__device__ __forceinline__ void mma16816(float* d, uint32_t a0, uint32_t a1, uint32_t a2, uint32_t a3,
                                         uint32_t b0, uint32_t b1){
    asm volatile("mma.sync.aligned.m16n8k16.row.col.f32.bf16.bf16.f32 "
        "{%0,%1,%2,%3}, {%4,%5,%6,%7}, {%8,%9}, {%0,%1,%2,%3};"
        : "+f"(d[0]), "+f"(d[1]), "+f"(d[2]), "+f"(d[3])
        : "r"(a0), "r"(a1), "r"(a2), "r"(a3), "r"(b0), "r"(b1));
}

// ---------------- device global scratch ----------------
__device__ float g_w3j[14][2197];
__device__ double g_psum[14][WCHUNK];
__device__ float g_M[8][3];
__device__ float g_pb[NN];
__device__ float g_qk[NB][NN][24];                 // 22 used
__device__ float g_rv[NB][NN][68];                 // 66 used
__device__ float g_ctx[NB][NN][68];                // 66 used
__device__ __nv_bfloat16 g_Phi[NB][NN][NN];        // exp(scores) hi, 134 MB
__device__ __nv_bfloat16 g_Plo[NB][NN][NN];        // exp(scores) lo, 134 MB
__device__ __nv_bfloat16 g_rvThi[NB][72][NN];      // transposed V hi, row 66 = ones
__device__ __nv_bfloat16 g_rvTlo[NB][72][NN];      // transposed V lo, row 66 = zeros

__constant__ int c_VAL_L[6][3] = {{4,0,4},{4,2,4},{6,2,4},{4,2,6},{6,0,6},{6,2,6}};
__constant__ int c_OUT_L[8][3] = {{4,4,4},{4,6,4},{6,4,4},{6,6,4},{4,4,6},{4,6,6},{6,4,6},{6,6,6}};
__constant__ int c_OUT_OFF[8] = {0,729,1782,2835,4356,5409,6930,8451};
__constant__ int c_VAL_OFF[6] = {0,81,486,1071,1656,1825};
__constant__ int c_VAL_SZ[6]  = {81,405,585,585,169,845};
__constant__ int c_OUT_SZ[8]  = {729,1053,1053,1521,1053,1521,1521,2197};

// ---------------- init: Wigner 3j ----------------
__device__ double d_cg(int l1,int l2,int l3,int m1,int m2,int m3,const double* F){
    if (m1+m2 != m3) return 0.0;
    double pA = (2.0*l3+1.0)*F[l3+l1-l2]*F[l3-l1+l2]*F[l1+l2-l3]/F[l1+l2+l3+1];
    double pB = F[l3+m3]*F[l3-m3]*F[l1-m1]*F[l1+m1]*F[l2-m2]*F[l2+m2];
    double pref = sqrt(pA*pB);
    double s = 0.0;
    for (int k = 0; k <= l1+l2-l3; k++){
        int d0=k, d1=l1+l2-l3-k, d2=l1-m1-k, d3=l2+m2-k, d4=l3-l2+m1+k, d5=l3-l1-m2+k;
        if (d0<0||d1<0||d2<0||d3<0||d4<0||d5<0) continue;
        double den = F[d0]*F[d1]*F[d2]*F[d3]*F[d4]*F[d5];
        s += ((k&1)? -1.0:1.0)/den;
    }
    return pref*s;
}

__device__ void build_q(int l, double2* q){
    int L = 2*l+1;
    for (int i=0;i<L*L;i++) q[i] = make_double2(0.0,0.0);
    double rs2 = 1.0/sqrt(2.0);
    for (int m=-l;m<0;m++){
        q[(l+m)*L + (l-m)] = make_double2(rs2, 0.0);
        q[(l+m)*L + (l+m)] = make_double2(0.0, -rs2);
    }
    q[l*L+l] = make_double2(1.0,0.0);
    for (int m=1;m<=l;m++){
        double sg = (m&1)? -1.0 : 1.0;
        q[(l+m)*L + (l+m)] = make_double2(sg*rs2, 0.0);
        q[(l+m)*L + (l-m)] = make_double2(0.0, sg*rs2);
    }
    double ph = (l % 4 == 0) ? 1.0 : -1.0;
    for (int i=0;i<L*L;i++){ q[i].x *= ph; q[i].y *= ph; }
}

__global__ void k_init_w3j_a(){
    int t = blockIdx.x, chunk = blockIdx.y;
    int l1,l2,l3;
    if (t<6){ l1=c_VAL_L[t][0]; l2=c_VAL_L[t][1]; l3=c_VAL_L[t][2]; }
    else    { l1=c_OUT_L[t-6][0]; l2=c_OUT_L[t-6][1]; l3=c_OUT_L[t-6][2]; }
    int I=2*l1+1, J=2*l2+1, K=2*l3+1;
    int IJK = I*J*K;
    int len = (IJK + WCHUNK - 1)/WCHUNK;
    int lo = chunk*len, hi = min(lo+len, IJK);
    __shared__ double sF[24];
    __shared__ double2 sQ1[169], sQ2[169], sQ3[169];
    __shared__ double sRed[128];
    int tid = threadIdx.x;
    if (tid < 24){ double r=1.0; for (int i=2;i<=tid;i++) r*= (double)i; sF[tid]=r; }
    if (tid==0) build_q(l1,sQ1);
    if (tid==1) build_q(l2,sQ2);
    if (tid==2) build_q(l3,sQ3);
    __syncthreads();
    double ss = 0.0;
    for (int idx=lo+tid; idx<hi; idx+=blockDim.x){
        int j = idx/(J*K); int r = idx - j*J*K; int l = r/K; int n = r - l*K;
        int ia[2] = {j, 2*l1-j};   int ni = (ia[1]==ia[0])?1:2;
        int kb[2] = {l, 2*l2-l};   int nk = (kb[1]==kb[0])?1:2;
        int mc[2] = {n, 2*l3-n};   int nm = (mc[1]==mc[0])?1:2;
        double acc = 0.0;
        for (int a=0;a<ni;a++){
            int i = ia[a];
            double2 q1 = sQ1[i*I+j];
            if (q1.x==0.0 && q1.y==0.0) continue;
            for (int bq=0;bq<nk;bq++){
                int k2 = kb[bq];
                double2 q2 = sQ2[k2*J+l];
                if (q2.x==0.0 && q2.y==0.0) continue;
                double px = q1.x*q2.x - q1.y*q2.y;
                double py = q1.x*q2.y + q1.y*q2.x;
                for (int cq=0;cq<nm;cq++){
                    int m = mc[cq];
                    double2 q3 = sQ3[m*K+n];
                    if (q3.x==0.0 && q3.y==0.0) continue;
                    double cg = d_cg(l1,l2,l3, i-l1, k2-l2, m-l3, sF);
                    if (cg==0.0) continue;
                    acc += (px*q3.x + py*q3.y)*cg;
                }
            }
        }
        g_w3j[t][idx] = (float)acc;
        ss += acc*acc;
    }
    sRed[tid] = ss;
    __syncthreads();
    for (int s=64;s>0;s>>=1){ if (tid<s) sRed[tid]+=sRed[tid+s]; __syncthreads(); }
    if (tid==0) g_psum[t][chunk] = sRed[0];
}

__global__ void k_init_w3j_b(){
    int t = blockIdx.x;
    int l3 = (t<6)? c_VAL_L[t][2] : c_OUT_L[t-6][2];
    int K = 2*l3+1;
    int IJK;
    if (t<6){ int l1=c_VAL_L[t][0], l2=c_VAL_L[t][1]; IJK=(2*l1+1)*(2*l2+1)*K; }
    else    { int l1=c_OUT_L[t-6][0], l2=c_OUT_L[t-6][1]; IJK=(2*l1+1)*(2*l2+1)*K; }
    __shared__ float sScale;
    if (threadIdx.x==0){
        double nrm2 = 0.0;
        for (int c=0;c<WCHUNK;c++) nrm2 += g_psum[t][c];
        double sc = (t<6)? sqrt((double)K/(3.0*CCH)) : sqrt((double)K/(4.0*CCH*CCH));
        sScale = (float)(sc/sqrt(nrm2));
    }
    __syncthreads();
    float s = sScale;
    for (int idx=threadIdx.x; idx<IJK; idx+=blockDim.x)
        g_w3j[t][idx] *= s;
}

// ---------------- init: M[p][qq] ----------------
__global__ void k_init_small(const float* __restrict__ w_lin_in, const float* __restrict__ w_val,
                             const float* __restrict__ w_out, const float* __restrict__ w_lin_out){
    int tid = threadIdx.x;
    if (tid < 24){
        int p = tid/3, qq = tid - p*3;
        int l1o = c_OUT_L[p][0], l2o = c_OUT_L[p][1], l3o = c_OUT_L[p][2];
        const float* wli_p = w_lin_in + (l1o==4 ? 0 : 8);
        const float* wlo   = w_lin_out + (l3o==4 ? 0 : 8);
        int q = (l2o==4 ? 0 : 3) + qq;
        const float* wli_q = w_lin_in + (c_VAL_L[q][0]==4 ? 0 : 8);
        float m = 0.f;
        for (int v=0; v<8; v++){
            float cpv = 0.f;
            for (int u=0; u<8; u++){
                float wu = wli_p[u];
                const float* wo = w_out + ((p*8+u)*8+v)*8;
                for (int w=0; w<8; w++) cpv += wu * wo[w] * wlo[w];
            }
            float aqv = 0.f;
            for (int u=0; u<8; u++) aqv += wli_q[u]*w_val[(q*8+u)*8+v];
            m += cpv*aqv;
        }
        g_M[p][qq] = m * 0.35355339059327373f;
    }
}

// ---------------- prep: qk features, pb, rv ----------------
__global__ void k_prep(const float* __restrict__ feat, const float* __restrict__ sh_lr,
                       const float* __restrict__ log_s, const float* __restrict__ pos_w,
                       const float* __restrict__ pos_b){
    __shared__ float sW[2670];
    __shared__ float sFt[8][22];
    __shared__ float sY[8][6];
    int tid = threadIdx.x, warp = tid>>5, lane = tid&31;
    for (int p=0;p<6;p++)
        for (int i=tid;i<c_VAL_SZ[p];i+=blockDim.x) sW[c_VAL_OFF[p]+i] = g_w3j[p][i];
    int node = blockIdx.x*8 + warp;
    int b = node >> 12, n = node & (NN-1);
    const float* f = feat + ((size_t)b*NN + n)*22;
    if (lane < 22) sFt[warp][lane] = f[lane];
    if (lane < 6)  sY[warp][lane]  = sh_lr[n*6+lane];
    __syncthreads();
    float n4=0.f, n6=0.f;
    #pragma unroll
    for (int d=0; d<9; d++){ float v=sFt[warp][d]; n4 += v*v; }
    #pragma unroll
    for (int d=9; d<22; d++){ float v=sFt[warp][d]; n6 += v*v; }
    float s4 = __expf(log_s[0]), s6 = __expf(log_s[1]);
    float r4 = sqrtf(s4)/fmaxf(sqrtf(n4), 1e-12f);
    float r6 = sqrtf(s6)/fmaxf(sqrtf(n6), 1e-12f);
    float* qk = &g_qk[b][n][0];
    if (lane < 9)        qk[lane] = sFt[warp][lane]*r4;
    else if (lane < 22)  qk[lane] = sFt[warp][lane]*r6;
    else if (lane < 24)  qk[lane] = 0.f;
    if (b==0 && lane==0){
        float pb = pos_b[0];
        for (int j=0;j<6;j++) pb += sY[warp][j]*pos_w[j];
        g_pb[n] = pb;
    }
    float* rv = &g_rv[b][n][0];
    for (int t=lane; t<68; t+=32){
        if (t >= 66){ rv[t] = 0.f; continue; }
        int p,k;
        if (t < 27){ p = t/9; k = t - p*9; } else { int u=t-27; p = 3 + u/13; k = u - (p-3)*13; }
        int l1 = c_VAL_L[p][0], l2 = c_VAL_L[p][1];
        int I = 2*l1+1, J = 2*l2+1, K = 2*c_VAL_L[p][2]+1;
        int foff = (l1==4)? 0 : 9;
        const float* w = sW + c_VAL_OFF[p];
        float r = 0.f;
        if (J == 1){
            float y0 = sY[warp][0];
            for (int i=0;i<I;i++) r += sFt[warp][foff+i]*y0*w[i*K+k];
        } else {
            for (int i=0;i<I;i++){
                float fi = sFt[warp][foff+i];
                #pragma unroll
                for (int j=0;j<5;j++) r += fi*sY[warp][1+j]*w[(i*5+j)*K+k];
            }
        }
        rv[t] = r;
    }
}

// ---------------- transpose rv -> bf16 hi/lo rvT[72][NN], row 66 = ones ----------------
__global__ void k_trans(){
    __shared__ float sm[64][68];
    int b = blockIdx.y;
    int n0 = blockIdx.x*64;
    int tid = threadIdx.x;
    for (int i=tid; i<64*17; i+=256){
        int r = i/17, f4 = i%17;
        *(float4*)&sm[r][f4*4] = *(const float4*)&g_rv[b][n0+r][f4*4];
    }
    __syncthreads();
    for (int t=tid; t<72*64; t+=256){
        int d = t/64, nn = t%64;
        float v;
        if (d < 66) v = sm[nn][d];
        else if (d == 66) v = 1.0f;
        else v = 0.0f;
        __nv_bfloat16 h = __float2bfloat16(v);
        float lo = v - __bfloat162float(h);
        g_rvThi[b][d][n0+nn] = h;
        g_rvTlo[b][d][n0+nn] = __float2bfloat16(lo);
    }
}

// ---------------- score kernel: P = exp(q·k + pb_k), bf16 hi/lo split ----------------
__global__ void __launch_bounds__(256) k_score(){
    __shared__ ull sQd[64][24];
    int b = blockIdx.z;
    int tid = threadIdx.x, lane = tid&31;
    int kbase = blockIdx.x*512 + (tid>>5)*64;
    int kA = kbase + 2*lane;
    ull kd[22];
    {
        const float* ka = &g_qk[b][kA][0];
        const float* kb2 = &g_qk[b][kA+1][0];
        #pragma unroll
        for (int d=0; d<22; d++){
            float a = ka[d], c = kb2[d];
            asm("mov.b64 %0, {%1,%2};" : "=l"(kd[d]) : "f"(a), "f"(c));
        }
    }
    ull pb2;
    {
        float a = g_pb[kA], c = g_pb[kA+1];
        asm("mov.b64 %0, {%1,%2};" : "=l"(pb2) : "f"(a), "f"(c));
    }
    int q0 = blockIdx.y*512;
    for (int qc=0; qc<8; qc++){
        int qb = q0 + qc*64;
        __syncthreads();
        for (int i=tid; i<64*22; i+=256){
            int q = i/22, d = i-q*22;
            float v = g_qk[b][qb+q][d];
            ull dv; asm("mov.b64 %0, {%1,%1};" : "=l"(dv) : "f"(v));
            sQd[q][d] = dv;
        }
        __syncthreads();
        #pragma unroll 2
        for (int q=0; q<64; q++){
            const ulonglong2* q2 = (const ulonglong2*)&sQd[q][0];
            ull a0 = pb2, a1 = 0ull;
            #pragma unroll
            for (int i=0;i<11;i++){
                ulonglong2 t = q2[i];
                fma2(a0, kd[2*i],   t.x);
                fma2(a1, kd[2*i+1], t.y);
            }
            ull s2 = add2(a0, a1);
            float s0,s1;
            asm("mov.b64 {%0,%1}, %2;" : "=f"(s0), "=f"(s1) : "l"(s2));
            float p0 = __expf(s0), p1 = __expf(s1);
            uint32_t hr;
            asm("cvt.rn.bf16x2.f32 %0, %1, %2;" : "=r"(hr) : "f"(p1), "f"(p0));
            float h0 = __uint_as_float(hr << 16);
            float h1 = __uint_as_float(hr & 0xffff0000u);
            float l0 = p0 - h0, l1 = p1 - h1;
            uint32_t lr;
            asm("cvt.rn.bf16x2.f32 %0, %1, %2;" : "=r"(lr) : "f"(l1), "f"(l0));
            *(uint32_t*)&g_Phi[b][qb+q][kA] = hr;
            *(uint32_t*)&g_Plo[b][qb+q][kA] = lr;
        }
    }
}

// ---------------- GEMM: ctx = normalize( P @ rvT^T ), 3-term bf16 compensation ----------------
// D = Ahi*Bhi + Ahi*Blo + Alo*Bhi   (drops Alo*Blo ~ 2^-18)
#define SA_STRIDE 72                       // bf16 elems per row (144 B, conflict-free ldmatrix)
#define SA_BYTES  (128*SA_STRIDE*2)        // 18432
#define SB_BYTES  (72*SA_STRIDE*2)         // 10368
#define GBUF      (2*SA_BYTES + 2*SB_BYTES) // 57600
#define GSM_TOTAL (3*GBUF)                 // 172800

__global__ void __launch_bounds__(256,1) k_gemm(){
    extern __shared__ __align__(16) char smem[];
    int b = blockIdx.y, qt = blockIdx.x;
    int tid = threadIdx.x, wid = tid>>5, lane = tid&31;

    const char* PHbase = (const char*)&g_Phi[b][qt*128][0];    // row stride 8192 B
    const char* PLbase = (const char*)&g_Plo[b][qt*128][0];
    const char* VHbase = (const char*)&g_rvThi[b][0][0];
    const char* VLbase = (const char*)&g_rvTlo[b][0][0];

    auto loadChunk = [&](int c){
        char* buf = smem + (c%3)*GBUF;
        size_t koff = (size_t)c*128;
        uint32_t sah = s2u(buf);
        uint32_t sal = sah + SA_BYTES;
        uint32_t sbh = sal + SA_BYTES;
        uint32_t sbl = sbh + SB_BYTES;
        #pragma unroll
        for (int j=0;j<4;j++){
            int idx = tid + j*256;
            int row = idx>>3, seg = idx&7;
            size_t go = (size_t)row*8192 + koff + seg*16;
            uint32_t so = row*(SA_STRIDE*2) + seg*16;
            cpasync16(sah + so, PHbase + go);
            cpasync16(sal + so, PLbase + go);
        }
        #pragma unroll
        for (int j=0;j<3;j++){
            int idx = tid + j*256;
            if (idx < 576){
                int row = idx>>3, seg = idx&7;
                size_t go = (size_t)row*8192 + koff + seg*16;
                uint32_t so = row*(SA_STRIDE*2) + seg*16;
                cpasync16(sbh + so, VHbase + go);
                cpasync16(sbl + so, VLbase + go);
            }
        }
        CP_COMMIT();
    };

    float acc[36];
    #pragma unroll
    for (int i=0;i<36;i++) acc[i]=0.f;

    loadChunk(0);
    loadChunk(1);

    int m0 = wid*16;
    for (int c=0; c<64; c++){
        if (c+2 < 64) loadChunk(c+2);
        if (c < 62)      asm volatile("cp.async.wait_group 2;" ::: "memory");
        else if (c == 62) asm volatile("cp.async.wait_group 1;" ::: "memory");
        else              asm volatile("cp.async.wait_group 0;" ::: "memory");
        __syncthreads();
        const char* buf = smem + (c%3)*GBUF;
        uint32_t sah = s2u(buf);
        uint32_t sal = sah + SA_BYTES;
        uint32_t sbh = sal + SA_BYTES;
        uint32_t sbl = sbh + SB_BYTES;
        uint32_t aOff  = ((m0 + (lane&15))*SA_STRIDE + (lane>>4)*8)*2;
        uint32_t b4Off = (((lane&7) + ((lane>>3)&1)*8)*SA_STRIDE + (lane>>4)*8)*2;
        uint32_t b2Off = ((64 + (lane&7))*SA_STRIDE + ((lane>>3)&1)*8)*2;
        #pragma unroll
        for (int ks=0; ks<4; ks++){
            uint32_t kofs = ks*16*2;
            uint32_t ah0,ah1,ah2,ah3, al0,al1,al2,al3;
            ldmx4(ah0,ah1,ah2,ah3, sah + aOff + kofs);
            ldmx4(al0,al1,al2,al3, sal + aOff + kofs);
            #pragma unroll
            for (int g=0; g<4; g++){
                uint32_t r0,r1,r2,r3;
                ldmx4(r0,r1,r2,r3, sbh + b4Off + g*(16*SA_STRIDE*2) + kofs);
                mma16816(acc + (2*g)*4,   ah0,ah1,ah2,ah3, r0, r2);
                mma16816(acc + (2*g+1)*4, ah0,ah1,ah2,ah3, r1, r3);
                mma16816(acc + (2*g)*4,   al0,al1,al2,al3, r0, r2);
                mma16816(acc + (2*g+1)*4, al0,al1,al2,al3, r1, r3);
                uint32_t s0,s1,s2l,s3;
                ldmx4(s0,s1,s2l,s3, sbl + b4Off + g*(16*SA_STRIDE*2) + kofs);
                mma16816(acc + (2*g)*4,   ah0,ah1,ah2,ah3, s0, s2l);
                mma16816(acc + (2*g+1)*4, ah0,ah1,ah2,ah3, s1, s3);
            }
            {
                uint32_t r0,r1;
                ldmx2(r0,r1, sbh + b2Off + kofs);
                mma16816(acc + 32, ah0,ah1,ah2,ah3, r0, r1);
                mma16816(acc + 32, al0,al1,al2,al3, r0, r1);
                uint32_t s0,s1;
                ldmx2(s0,s1, sbl + b2Off + kofs);
                mma16816(acc + 32, ah0,ah1,ah2,ah3, s0, s1);
            }
        }
        __syncthreads();
    }

    // epilogue: col 66 = row sum; owned by lane%4==1 (acc[32] upper row, acc[34] lower)
    const unsigned FULL = 0xffffffffu;
    float s_hi = __shfl_sync(FULL, acc[32], (lane & 0x1c) + 1);
    float s_lo = __shfl_sync(FULL, acc[34], (lane & 0x1c) + 1);
    float inv_hi = 1.0f/s_hi, inv_lo = 1.0f/s_lo;
    int r0 = qt*128 + m0 + (lane>>2);
    int r1 = r0 + 8;
    int colb = 2*(lane&3);
    #pragma unroll
    for (int nt=0; nt<9; nt++){
        int j = nt*8 + colb;
        if (j < 66){
            float v0 = acc[nt*4+0]*inv_hi, v1 = acc[nt*4+1]*inv_hi;
            ull pk; asm("mov.b64 %0, {%1,%2};" : "=l"(pk) : "f"(v0), "f"(v1));
            *(ull*)&g_ctx[b][r0][j] = pk;
            float w0 = acc[nt*4+2]*inv_lo, w1 = acc[nt*4+3]*inv_lo;
            ull pk2; asm("mov.b64 %0, {%1,%2};" : "=l"(pk2) : "f"(w0), "f"(w1));
            *(ull*)&g_ctx[b][r1][j] = pk2;
        }
    }
}

// ---------------- out ----------------
template<int I,int J,int K>
__device__ __forceinline__ float path_term(const float* fp, const float* c0, const float* c1, const float* c2,
                                           float m0, float m1, float m2, const float* w, int k){
    float e[J];
    #pragma unroll
    for (int j=0;j<J;j++) e[j] = m0*c0[j] + m1*c1[j] + m2*c2[j];
    float d = 0.f;
    for (int i=0;i<I;i++){
        float fi = fp[i];
        #pragma unroll
        for (int j=0;j<J;j++) d += fi*e[j]*w[(i*J+j)*K+k];
    }
    return d;
}

__global__ void k_out(const float* __restrict__ feat, float* __restrict__ out){
    __shared__ float sW[10648];
    __shared__ float sFt[8][22];
    __shared__ float sC[8][66];
    int tid = threadIdx.x, warp = tid>>5, lane = tid&31;
    for (int p=0;p<8;p++)
        for (int i=tid;i<c_OUT_SZ[p];i+=blockDim.x) sW[c_OUT_OFF[p]+i] = g_w3j[6+p][i];
    int node = blockIdx.x*8 + warp;
    int b = node >> 12, n = node & (NN-1);
    if (lane < 22) sFt[warp][lane] = feat[((size_t)b*NN+n)*22 + lane];
    for (int t=lane; t<66; t+=32) sC[warp][t] = g_ctx[b][n][t];
    __syncthreads();
    if (lane < 22){
        const float* F = sFt[warp];
        const float* C = sC[warp];
        float d;
        if (lane < 9){
            int k = lane;
            d  = path_term<9 ,9 ,9>(F  , C   , C+9 , C+18, g_M[0][0],g_M[0][1],g_M[0][2], sW+c_OUT_OFF[0], k);
            d += path_term<9 ,13,9>(F  , C+27, C+40, C+53, g_M[1][0],g_M[1][1],g_M[1][2], sW+c_OUT_OFF[1], k);
            d += path_term<13,9 ,9>(F+9, C   , C+9 , C+18, g_M[2][0],g_M[2][1],g_M[2][2], sW+c_OUT_OFF[2], k);
            d += path_term<13,13,9>(F+9, C+27, C+40, C+53, g_M[3][0],g_M[3][1],g_M[3][2], sW+c_OUT_OFF[3], k);
        } else {
            int k = lane - 9;
            d  = path_term<9 ,9 ,13>(F  , C   , C+9 , C+18, g_M[4][0],g_M[4][1],g_M[4][2], sW+c_OUT_OFF[4], k);
            d += path_term<9 ,13,13>(F  , C+27, C+40, C+53, g_M[5][0],g_M[5][1],g_M[5][2], sW+c_OUT_OFF[5], k);
            d += path_term<13,9 ,13>(F+9, C   , C+9 , C+18, g_M[6][0],g_M[6][1],g_M[6][2], sW+c_OUT_OFF[6], k);
            d += path_term<13,13,13>(F+9, C+27, C+40, C+53, g_M[7][0],g_M[7][1],g_M[7][2], sW+c_OUT_OFF[7], k);
        }
        out[((size_t)b*NN+n)*22 + lane] = d;
    }
}

// ---------------- launch ----------------
extern "C" void kernel_launch(void* const* d_in, const int* in_sizes, int n_in,
                              void* d_out, int out_size){
    const float* feat      = (const float*)d_in[0];
    const float* sh_lr     = (const float*)d_in[1];
    const float* log_s     = (const float*)d_in[2];
    const float* pos_w     = (const float*)d_in[3];
    const float* pos_b     = (const float*)d_in[4];
    const float* w_lin_in  = (const float*)d_in[5];
    const float* w_val     = (const float*)d_in[6];
    const float* w_out     = (const float*)d_in[7];
    const float* w_lin_out = (const float*)d_in[8];
    float* out = (float*)d_out;

    cudaFuncSetAttribute(k_gemm, cudaFuncAttributeMaxDynamicSharedMemorySize, GSM_TOTAL);

    dim3 gi(14, WCHUNK);
    k_init_w3j_a<<<gi, 128>>>();
    k_init_w3j_b<<<14, 128>>>();
    k_init_small<<<1,32>>>(w_lin_in, w_val, w_out, w_lin_out);
    k_prep<<<(NB*NN)/8, 256>>>(feat, sh_lr, log_s, pos_w, pos_b);
    k_trans<<<dim3(NN/64, NB), 256>>>();
    k_score<<<dim3(8, 8, NB), 256>>>();
    k_gemm<<<dim3(NN/128, NB), 256, GSM_TOTAL>>>();
    k_out<<<(NB*NN)/8, 256>>>(feat, out);
}

// round 8
// speedup vs baseline: 4.9112x; 1.3279x over previous
#include <cuda_runtime.h>
#include <cuda_bf16.h>
#include <math.h>
#include <stdint.h>

#define NB 4
#define NN 4096
#define CCH 8
#define WCHUNK 64

typedef unsigned long long ull;

__device__ __forceinline__ uint32_t s2u(const void* p){
    uint32_t a;
    asm("{ .reg .u64 t; cvta.to.shared.u64 t, %1; cvt.u32.u64 %0, t; }" : "=r"(a) : "l"(p));
    return a;
}
__device__ __forceinline__ void cpasync16(uint32_t dst, const void* src){
    asm volatile("cp.async.cg.shared.global [%0], [%1], 16;" :: "r"(dst), "l"(src));
}
#define CP_COMMIT() asm volatile("cp.async.commit_group;" ::: "memory")

__device__ __forceinline__ void ldmx4(uint32_t& r0, uint32_t& r1, uint32_t& r2, uint32_t& r3, uint32_t a){
    asm volatile("ldmatrix.sync.aligned.m8n8.x4.shared.b16 {%0,%1,%2,%3}, [%4];"
        : "=r"(r0), "=r"(r1), "=r"(r2), "=r"(r3) : "r"(a));
}
__device__ __forceinline__ void ldmx2(uint32_t& r0, uint32_t& r1, uint32_t a){
    asm volatile("ldmatrix.sync.aligned.m8n8.x2.shared.b16 {%0,%1}, [%2];"
        : "=r"(r0), "=r"(r1) : "r"(a));
}
__device__ __forceinline__ void mma16816(float* d, uint32_t a0, uint32_t a1, uint32_t a2, uint32_t a3,
                                         uint32_t b0, uint32_t b1){
    asm volatile("mma.sync.aligned.m16n8k16.row.col.f32.bf16.bf16.f32 "
        "{%0,%1,%2,%3}, {%4,%5,%6,%7}, {%8,%9}, {%0,%1,%2,%3};"
        : "+f"(d[0]), "+f"(d[1]), "+f"(d[2]), "+f"(d[3])
        : "r"(a0), "r"(a1), "r"(a2), "r"(a3), "r"(b0), "r"(b1));
}
__device__ __forceinline__ uint32_t cvtpack(float hi, float lo){
    uint32_t r; asm("cvt.rn.bf16x2.f32 %0, %1, %2;" : "=r"(r) : "f"(hi), "f"(lo)); return r;
}

// ---------------- device global scratch ----------------
__device__ float g_w3j[14][2197];
__device__ double g_psum[14][WCHUNK];
__device__ float g_M[8][3];
__device__ float g_rv[NB][NN][68];                 // 66 used
__device__ float g_ctx[NB][NN][68];                // 66 used
__device__ __nv_bfloat16 g_fqh[NB][NN][32];        // query feats hi (22 + feat22=1)
__device__ __nv_bfloat16 g_fql[NB][NN][32];        // query feats lo
__device__ __nv_bfloat16 g_fkh[NB][NN][32];        // key feats hi (22 + feat22=pb)
__device__ __nv_bfloat16 g_fkl[NB][NN][32];        // key feats lo
__device__ __nv_bfloat16 g_rvThi[NB][72][NN];      // transposed V hi, row 66 = ones
__device__ __nv_bfloat16 g_rvTlo[NB][72][NN];      // transposed V lo

__constant__ int c_VAL_L[6][3] = {{4,0,4},{4,2,4},{6,2,4},{4,2,6},{6,0,6},{6,2,6}};
__constant__ int c_OUT_L[8][3] = {{4,4,4},{4,6,4},{6,4,4},{6,6,4},{4,4,6},{4,6,6},{6,4,6},{6,6,6}};
__constant__ int c_OUT_OFF[8] = {0,729,1782,2835,4356,5409,6930,8451};
__constant__ int c_VAL_OFF[6] = {0,81,486,1071,1656,1825};
__constant__ int c_VAL_SZ[6]  = {81,405,585,585,169,845};
__constant__ int c_OUT_SZ[8]  = {729,1053,1053,1521,1053,1521,1521,2197};

// ---------------- init: Wigner 3j ----------------
__device__ double d_cg(int l1,int l2,int l3,int m1,int m2,int m3,const double* F){
    if (m1+m2 != m3) return 0.0;
    double pA = (2.0*l3+1.0)*F[l3+l1-l2]*F[l3-l1+l2]*F[l1+l2-l3]/F[l1+l2+l3+1];
    double pB = F[l3+m3]*F[l3-m3]*F[l1-m1]*F[l1+m1]*F[l2-m2]*F[l2+m2];
    double pref = sqrt(pA*pB);
    double s = 0.0;
    for (int k = 0; k <= l1+l2-l3; k++){
        int d0=k, d1=l1+l2-l3-k, d2=l1-m1-k, d3=l2+m2-k, d4=l3-l2+m1+k, d5=l3-l1-m2+k;
        if (d0<0||d1<0||d2<0||d3<0||d4<0||d5<0) continue;
        double den = F[d0]*F[d1]*F[d2]*F[d3]*F[d4]*F[d5];
        s += ((k&1)? -1.0:1.0)/den;
    }
    return pref*s;
}

__device__ void build_q(int l, double2* q){
    int L = 2*l+1;
    for (int i=0;i<L*L;i++) q[i] = make_double2(0.0,0.0);
    double rs2 = 1.0/sqrt(2.0);
    for (int m=-l;m<0;m++){
        q[(l+m)*L + (l-m)] = make_double2(rs2, 0.0);
        q[(l+m)*L + (l+m)] = make_double2(0.0, -rs2);
    }
    q[l*L+l] = make_double2(1.0,0.0);
    for (int m=1;m<=l;m++){
        double sg = (m&1)? -1.0 : 1.0;
        q[(l+m)*L + (l+m)] = make_double2(sg*rs2, 0.0);
        q[(l+m)*L + (l-m)] = make_double2(0.0, sg*rs2);
    }
    double ph = (l % 4 == 0) ? 1.0 : -1.0;
    for (int i=0;i<L*L;i++){ q[i].x *= ph; q[i].y *= ph; }
}

__global__ void k_init_w3j_a(){
    int t = blockIdx.x, chunk = blockIdx.y;
    int l1,l2,l3;
    if (t<6){ l1=c_VAL_L[t][0]; l2=c_VAL_L[t][1]; l3=c_VAL_L[t][2]; }
    else    { l1=c_OUT_L[t-6][0]; l2=c_OUT_L[t-6][1]; l3=c_OUT_L[t-6][2]; }
    int I=2*l1+1, J=2*l2+1, K=2*l3+1;
    int IJK = I*J*K;
    int len = (IJK + WCHUNK - 1)/WCHUNK;
    int lo = chunk*len, hi = min(lo+len, IJK);
    __shared__ double sF[24];
    __shared__ double2 sQ1[169], sQ2[169], sQ3[169];
    __shared__ double sRed[128];
    int tid = threadIdx.x;
    if (tid < 24){ double r=1.0; for (int i=2;i<=tid;i++) r*= (double)i; sF[tid]=r; }
    if (tid==0) build_q(l1,sQ1);
    if (tid==1) build_q(l2,sQ2);
    if (tid==2) build_q(l3,sQ3);
    __syncthreads();
    double ss = 0.0;
    for (int idx=lo+tid; idx<hi; idx+=blockDim.x){
        int j = idx/(J*K); int r = idx - j*J*K; int l = r/K; int n = r - l*K;
        int ia[2] = {j, 2*l1-j};   int ni = (ia[1]==ia[0])?1:2;
        int kb[2] = {l, 2*l2-l};   int nk = (kb[1]==kb[0])?1:2;
        int mc[2] = {n, 2*l3-n};   int nm = (mc[1]==mc[0])?1:2;
        double acc = 0.0;
        for (int a=0;a<ni;a++){
            int i = ia[a];
            double2 q1 = sQ1[i*I+j];
            if (q1.x==0.0 && q1.y==0.0) continue;
            for (int bq=0;bq<nk;bq++){
                int k2 = kb[bq];
                double2 q2 = sQ2[k2*J+l];
                if (q2.x==0.0 && q2.y==0.0) continue;
                double px = q1.x*q2.x - q1.y*q2.y;
                double py = q1.x*q2.y + q1.y*q2.x;
                for (int cq=0;cq<nm;cq++){
                    int m = mc[cq];
                    double2 q3 = sQ3[m*K+n];
                    if (q3.x==0.0 && q3.y==0.0) continue;
                    double cg = d_cg(l1,l2,l3, i-l1, k2-l2, m-l3, sF);
                    if (cg==0.0) continue;
                    acc += (px*q3.x + py*q3.y)*cg;
                }
            }
        }
        g_w3j[t][idx] = (float)acc;
        ss += acc*acc;
    }
    sRed[tid] = ss;
    __syncthreads();
    for (int s=64;s>0;s>>=1){ if (tid<s) sRed[tid]+=sRed[tid+s]; __syncthreads(); }
    if (tid==0) g_psum[t][chunk] = sRed[0];
}

__global__ void k_init_w3j_b(){
    int t = blockIdx.x;
    int l3 = (t<6)? c_VAL_L[t][2] : c_OUT_L[t-6][2];
    int K = 2*l3+1;
    int IJK;
    if (t<6){ int l1=c_VAL_L[t][0], l2=c_VAL_L[t][1]; IJK=(2*l1+1)*(2*l2+1)*K; }
    else    { int l1=c_OUT_L[t-6][0], l2=c_OUT_L[t-6][1]; IJK=(2*l1+1)*(2*l2+1)*K; }
    __shared__ float sScale;
    if (threadIdx.x==0){
        double nrm2 = 0.0;
        for (int c=0;c<WCHUNK;c++) nrm2 += g_psum[t][c];
        double sc = (t<6)? sqrt((double)K/(3.0*CCH)) : sqrt((double)K/(4.0*CCH*CCH));
        sScale = (float)(sc/sqrt(nrm2));
    }
    __syncthreads();
    float s = sScale;
    for (int idx=threadIdx.x; idx<IJK; idx+=blockDim.x)
        g_w3j[t][idx] *= s;
}

// ---------------- init: M[p][qq] ----------------
__global__ void k_init_small(const float* __restrict__ w_lin_in, const float* __restrict__ w_val,
                             const float* __restrict__ w_out, const float* __restrict__ w_lin_out){
    int tid = threadIdx.x;
    if (tid < 24){
        int p = tid/3, qq = tid - p*3;
        int l1o = c_OUT_L[p][0], l2o = c_OUT_L[p][1], l3o = c_OUT_L[p][2];
        const float* wli_p = w_lin_in + (l1o==4 ? 0 : 8);
        const float* wlo   = w_lin_out + (l3o==4 ? 0 : 8);
        int q = (l2o==4 ? 0 : 3) + qq;
        const float* wli_q = w_lin_in + (c_VAL_L[q][0]==4 ? 0 : 8);
        float m = 0.f;
        for (int v=0; v<8; v++){
            float cpv = 0.f;
            for (int u=0; u<8; u++){
                float wu = wli_p[u];
                const float* wo = w_out + ((p*8+u)*8+v)*8;
                for (int w=0; w<8; w++) cpv += wu * wo[w] * wlo[w];
            }
            float aqv = 0.f;
            for (int u=0; u<8; u++) aqv += wli_q[u]*w_val[(q*8+u)*8+v];
            m += cpv*aqv;
        }
        g_M[p][qq] = m * 0.35355339059327373f;
    }
}

// ---------------- prep: per-node bf16 hi/lo features, rv ----------------
__global__ void k_prep(const float* __restrict__ feat, const float* __restrict__ sh_lr,
                       const float* __restrict__ log_s, const float* __restrict__ pos_w,
                       const float* __restrict__ pos_b){
    __shared__ float sW[2670];
    __shared__ float sFt[8][22];
    __shared__ float sY[8][6];
    int tid = threadIdx.x, warp = tid>>5, lane = tid&31;
    for (int p=0;p<6;p++)
        for (int i=tid;i<c_VAL_SZ[p];i+=blockDim.x) sW[c_VAL_OFF[p]+i] = g_w3j[p][i];
    int node = blockIdx.x*8 + warp;
    int b = node >> 12, n = node & (NN-1);
    const float* f = feat + ((size_t)b*NN + n)*22;
    if (lane < 22) sFt[warp][lane] = f[lane];
    if (lane < 6)  sY[warp][lane]  = sh_lr[n*6+lane];
    __syncthreads();
    float n4=0.f, n6=0.f;
    #pragma unroll
    for (int d=0; d<9; d++){ float v=sFt[warp][d]; n4 += v*v; }
    #pragma unroll
    for (int d=9; d<22; d++){ float v=sFt[warp][d]; n6 += v*v; }
    float s4 = __expf(log_s[0]), s6 = __expf(log_s[1]);
    float r4 = sqrtf(s4)/fmaxf(sqrtf(n4), 1e-12f);
    float r6 = sqrtf(s6)/fmaxf(sqrtf(n6), 1e-12f);
    // pb for this node
    float pb = pos_b[0];
    #pragma unroll
    for (int j=0;j<6;j++) pb += sY[warp][j]*pos_w[j];
    // per-lane feature value (lane = feature index 0..31)
    float v;
    if (lane < 9)       v = sFt[warp][lane]*r4;
    else if (lane < 22) v = sFt[warp][lane]*r6;
    else                v = 0.f;
    float vq = (lane==22) ? 1.0f : v;
    float vk = (lane==22) ? pb   : v;
    {
        __nv_bfloat16 hq = __float2bfloat16(vq);
        g_fqh[b][n][lane] = hq;
        g_fql[b][n][lane] = __float2bfloat16(vq - __bfloat162float(hq));
        __nv_bfloat16 hk = __float2bfloat16(vk);
        g_fkh[b][n][lane] = hk;
        g_fkl[b][n][lane] = __float2bfloat16(vk - __bfloat162float(hk));
    }
    float* rv = &g_rv[b][n][0];
    for (int t=lane; t<68; t+=32){
        if (t >= 66){ rv[t] = 0.f; continue; }
        int p,k;
        if (t < 27){ p = t/9; k = t - p*9; } else { int u=t-27; p = 3 + u/13; k = u - (p-3)*13; }
        int l1 = c_VAL_L[p][0], l2 = c_VAL_L[p][1];
        int I = 2*l1+1, J = 2*l2+1, K = 2*c_VAL_L[p][2]+1;
        int foff = (l1==4)? 0 : 9;
        const float* w = sW + c_VAL_OFF[p];
        float r = 0.f;
        if (J == 1){
            float y0 = sY[warp][0];
            for (int i=0;i<I;i++) r += sFt[warp][foff+i]*y0*w[i*K+k];
        } else {
            for (int i=0;i<I;i++){
                float fi = sFt[warp][foff+i];
                #pragma unroll
                for (int j=0;j<5;j++) r += fi*sY[warp][1+j]*w[(i*5+j)*K+k];
            }
        }
        rv[t] = r;
    }
}

// ---------------- transpose rv -> bf16 hi/lo rvT[72][NN], row 66 = ones ----------------
__global__ void k_trans(){
    __shared__ float sm[64][68];
    int b = blockIdx.y;
    int n0 = blockIdx.x*64;
    int tid = threadIdx.x;
    for (int i=tid; i<64*17; i+=256){
        int r = i/17, f4 = i%17;
        *(float4*)&sm[r][f4*4] = *(const float4*)&g_rv[b][n0+r][f4*4];
    }
    __syncthreads();
    for (int t=tid; t<72*64; t+=256){
        int d = t/64, nn = t%64;
        float v;
        if (d < 66) v = sm[nn][d];
        else if (d == 66) v = 1.0f;
        else v = 0.0f;
        __nv_bfloat16 h = __float2bfloat16(v);
        float lo = v - __bfloat162float(h);
        g_rvThi[b][d][n0+nn] = h;
        g_rvTlo[b][d][n0+nn] = __float2bfloat16(lo);
    }
}

// ---------------- fused attention: S=QK^T (MMA) -> exp in regs -> P@V (MMA) ----------------
// Per CTA: 128 queries x all 4096 keys in 64-key chunks.
// 3-term bf16 compensation on both GEMMs. Ones-column of V gives softmax denom.
// SMEM layout (bytes from base):
//   Qhi [128][40]  @ 0       (10240)
//   Qlo [128][40]  @ 10240   (10240)
//   K stage s: Khi [64][40] @ 20480+s*10240, Klo @ +5120
//   V stage s: Vhi [72][72] @ 40960+s*20736, Vlo @ +10368
#define ATT_SMEM 82432

__global__ void __launch_bounds__(256,1) k_attn(){
    extern __shared__ __align__(16) char smem[];
    uint32_t sb = s2u(smem);
    int b = blockIdx.y, qt = blockIdx.x;
    int tid = threadIdx.x, wid = tid>>5, lane = tid&31;
    int m0 = wid*16;

    // ---- Q prefetch (once) + chunk 0 ----
    auto loadQ = [&](){
        #pragma unroll
        for (int j=0;j<4;j++){
            int idx = tid + j*256;        // 1024 = 2 planes * 128 rows * 4 segs
            int plane = idx>>9, rr = idx&511;
            int row = rr>>2, seg = rr&3;
            const __nv_bfloat16* src = plane ? &g_fql[b][qt*128+row][seg*8] : &g_fqh[b][qt*128+row][seg*8];
            cpasync16(sb + plane*10240 + row*80 + seg*16, src);
        }
    };
    auto loadK = [&](int c){
        uint32_t kb2 = sb + 20480 + (c&1)*10240;
        int kbase = c*64;
        #pragma unroll
        for (int j=0;j<2;j++){
            int idx = tid + j*256;        // 512 = 2 planes * 64 rows * 4 segs
            int plane = idx>>8, rr = idx&255;
            int row = rr>>2, seg = rr&3;
            const __nv_bfloat16* src = plane ? &g_fkl[b][kbase+row][seg*8] : &g_fkh[b][kbase+row][seg*8];
            cpasync16(kb2 + plane*5120 + row*80 + seg*16, src);
        }
    };
    auto loadV = [&](int c){
        uint32_t vb = sb + 40960 + (c&1)*20736;
        int kbase = c*64;
        #pragma unroll
        for (int j=0;j<5;j++){
            int idx = tid + j*256;        // 1152 = 2 planes * 72 rows * 8 segs
            if (idx < 1152){
                int plane = idx/576, rr = idx - plane*576;
                int row = rr>>3, seg = rr&7;
                const __nv_bfloat16* src = plane ? &g_rvTlo[b][row][kbase+seg*8] : &g_rvThi[b][row][kbase+seg*8];
                cpasync16(vb + plane*10368 + row*144 + seg*16, src);
            }
        }
    };

    loadQ(); loadK(0); loadV(0); CP_COMMIT();

    float acc[36];
    #pragma unroll
    for (int i=0;i<36;i++) acc[i]=0.f;

    uint32_t qh[2][4], ql[2][4];
    bool qloaded = false;

    for (int c=0; c<64; c++){
        if (c+1 < 64){ loadK(c+1); loadV(c+1); CP_COMMIT(); }
        if (c+1 < 64) asm volatile("cp.async.wait_group 1;" ::: "memory");
        else          asm volatile("cp.async.wait_group 0;" ::: "memory");
        __syncthreads();

        if (!qloaded){
            uint32_t aQh = sb +          ((m0 + (lane&15))*40 + (lane>>4)*8)*2;
            uint32_t aQl = sb + 10240u + ((m0 + (lane&15))*40 + (lane>>4)*8)*2;
            #pragma unroll
            for (int ks=0; ks<2; ks++){
                ldmx4(qh[ks][0],qh[ks][1],qh[ks][2],qh[ks][3], aQh + ks*32);
                ldmx4(ql[ks][0],ql[ks][1],ql[ks][2],ql[ks][3], aQl + ks*32);
            }
            qloaded = true;
        }

        uint32_t khi = sb + 20480 + (c&1)*10240;
        uint32_t klo = khi + 5120;
        uint32_t vhi = sb + 40960 + (c&1)*20736;
        uint32_t vlo = vhi + 10368;
        uint32_t b4Off = (((lane&7) + ((lane>>3)&1)*8)*72 + (lane>>4)*8)*2;
        uint32_t b2Off = ((64 + (lane&7))*72 + ((lane>>3)&1)*8)*2;
        uint32_t kRow  = ((lane&7)*40 + ((lane>>3)&1)*8)*2;

        #pragma unroll
        for (int ks2=0; ks2<4; ks2++){
            // --- scores for key n-tiles 2*ks2, 2*ks2+1 ---
            float S[8];
            #pragma unroll
            for (int i=0;i<8;i++) S[i]=0.f;
            #pragma unroll
            for (int half=0; half<2; half++){
                int nt = 2*ks2 + half;
                uint32_t kbase_off = nt*8*40*2;
                #pragma unroll
                for (int ks=0; ks<2; ks++){
                    uint32_t bh0,bh1, bl0,bl1;
                    ldmx2(bh0,bh1, khi + kbase_off + kRow + ks*32);
                    mma16816(S+half*4, qh[ks][0],qh[ks][1],qh[ks][2],qh[ks][3], bh0, bh1);
                    mma16816(S+half*4, ql[ks][0],ql[ks][1],ql[ks][2],ql[ks][3], bh0, bh1);
                    ldmx2(bl0,bl1, klo + kbase_off + kRow + ks*32);
                    mma16816(S+half*4, qh[ks][0],qh[ks][1],qh[ks][2],qh[ks][3], bl0, bl1);
                }
            }
            // --- exp + hi/lo A-frag build ---
            float p[8];
            #pragma unroll
            for (int i=0;i<8;i++) p[i] = __expf(S[i]);
            uint32_t ah[4], al[4];
            ah[0] = cvtpack(p[1], p[0]);
            ah[1] = cvtpack(p[3], p[2]);
            ah[2] = cvtpack(p[5], p[4]);
            ah[3] = cvtpack(p[7], p[6]);
            #pragma unroll
            for (int i=0;i<4;i++){
                float hlo = __uint_as_float(ah[i] << 16);
                float hhi = __uint_as_float(ah[i] & 0xffff0000u);
                al[i] = cvtpack(p[2*i+1] - hhi, p[2*i] - hlo);
            }
            // --- P @ V for this 16-key step ---
            uint32_t kofs = ks2*32;
            #pragma unroll
            for (int g=0; g<4; g++){
                uint32_t r0,r1,r2,r3;
                ldmx4(r0,r1,r2,r3, vhi + b4Off + g*(16*72*2) + kofs);
                mma16816(acc + (2*g)*4,   ah[0],ah[1],ah[2],ah[3], r0, r2);
                mma16816(acc + (2*g+1)*4, ah[0],ah[1],ah[2],ah[3], r1, r3);
                mma16816(acc + (2*g)*4,   al[0],al[1],al[2],al[3], r0, r2);
                mma16816(acc + (2*g+1)*4, al[0],al[1],al[2],al[3], r1, r3);
                uint32_t s0,s1,s2,s3;
                ldmx4(s0,s1,s2,s3, vlo + b4Off + g*(16*72*2) + kofs);
                mma16816(acc + (2*g)*4,   ah[0],ah[1],ah[2],ah[3], s0, s2);
                mma16816(acc + (2*g+1)*4, ah[0],ah[1],ah[2],ah[3], s1, s3);
            }
            {
                uint32_t r0,r1, s0,s1;
                ldmx2(r0,r1, vhi + b2Off + kofs);
                mma16816(acc + 32, ah[0],ah[1],ah[2],ah[3], r0, r1);
                mma16816(acc + 32, al[0],al[1],al[2],al[3], r0, r1);
                ldmx2(s0,s1, vlo + b2Off + kofs);
                mma16816(acc + 32, ah[0],ah[1],ah[2],ah[3], s0, s1);
            }
        }
        __syncthreads();
    }

    // epilogue: col 66 = row sum; owner lane has (lane&3)==1, d0/d2
    const unsigned FULL = 0xffffffffu;
    float s_hi = __shfl_sync(FULL, acc[32], (lane & 0x1c) + 1);
    float s_lo = __shfl_sync(FULL, acc[34], (lane & 0x1c) + 1);
    float inv_hi = 1.0f/s_hi, inv_lo = 1.0f/s_lo;
    int r0 = qt*128 + m0 + (lane>>2);
    int r1 = r0 + 8;
    int colb = 2*(lane&3);
    #pragma unroll
    for (int nt=0; nt<9; nt++){
        int j = nt*8 + colb;
        if (j < 66){
            float v0 = acc[nt*4+0]*inv_hi, v1 = acc[nt*4+1]*inv_hi;
            ull pk; asm("mov.b64 %0, {%1,%2};" : "=l"(pk) : "f"(v0), "f"(v1));
            *(ull*)&g_ctx[b][r0][j] = pk;
            float w0 = acc[nt*4+2]*inv_lo, w1 = acc[nt*4+3]*inv_lo;
            ull pk2; asm("mov.b64 %0, {%1,%2};" : "=l"(pk2) : "f"(w0), "f"(w1));
            *(ull*)&g_ctx[b][r1][j] = pk2;
        }
    }
}

// ---------------- out ----------------
template<int I,int J,int K>
__device__ __forceinline__ float path_term(const float* fp, const float* c0, const float* c1, const float* c2,
                                           float m0, float m1, float m2, const float* w, int k){
    float e[J];
    #pragma unroll
    for (int j=0;j<J;j++) e[j] = m0*c0[j] + m1*c1[j] + m2*c2[j];
    float d = 0.f;
    for (int i=0;i<I;i++){
        float fi = fp[i];
        #pragma unroll
        for (int j=0;j<J;j++) d += fi*e[j]*w[(i*J+j)*K+k];
    }
    return d;
}

__global__ void k_out(const float* __restrict__ feat, float* __restrict__ out){
    __shared__ float sW[10648];
    __shared__ float sFt[8][22];
    __shared__ float sC[8][66];
    int tid = threadIdx.x, warp = tid>>5, lane = tid&31;
    for (int p=0;p<8;p++)
        for (int i=tid;i<c_OUT_SZ[p];i+=blockDim.x) sW[c_OUT_OFF[p]+i] = g_w3j[6+p][i];
    int node = blockIdx.x*8 + warp;
    int b = node >> 12, n = node & (NN-1);
    if (lane < 22) sFt[warp][lane] = feat[((size_t)b*NN+n)*22 + lane];
    for (int t=lane; t<66; t+=32) sC[warp][t] = g_ctx[b][n][t];
    __syncthreads();
    if (lane < 22){
        const float* F = sFt[warp];
        const float* C = sC[warp];
        float d;
        if (lane < 9){
            int k = lane;
            d  = path_term<9 ,9 ,9>(F  , C   , C+9 , C+18, g_M[0][0],g_M[0][1],g_M[0][2], sW+c_OUT_OFF[0], k);
            d += path_term<9 ,13,9>(F  , C+27, C+40, C+53, g_M[1][0],g_M[1][1],g_M[1][2], sW+c_OUT_OFF[1], k);
            d += path_term<13,9 ,9>(F+9, C   , C+9 , C+18, g_M[2][0],g_M[2][1],g_M[2][2], sW+c_OUT_OFF[2], k);
            d += path_term<13,13,9>(F+9, C+27, C+40, C+53, g_M[3][0],g_M[3][1],g_M[3][2], sW+c_OUT_OFF[3], k);
        } else {
            int k = lane - 9;
            d  = path_term<9 ,9 ,13>(F  , C   , C+9 , C+18, g_M[4][0],g_M[4][1],g_M[4][2], sW+c_OUT_OFF[4], k);
            d += path_term<9 ,13,13>(F  , C+27, C+40, C+53, g_M[5][0],g_M[5][1],g_M[5][2], sW+c_OUT_OFF[5], k);
            d += path_term<13,9 ,13>(F+9, C   , C+9 , C+18, g_M[6][0],g_M[6][1],g_M[6][2], sW+c_OUT_OFF[6], k);
            d += path_term<13,13,13>(F+9, C+27, C+40, C+53, g_M[7][0],g_M[7][1],g_M[7][2], sW+c_OUT_OFF[7], k);
        }
        out[((size_t)b*NN+n)*22 + lane] = d;
    }
}

// ---------------- launch ----------------
extern "C" void kernel_launch(void* const* d_in, const int* in_sizes, int n_in,
                              void* d_out, int out_size){
    const float* feat      = (const float*)d_in[0];
    const float* sh_lr     = (const float*)d_in[1];
    const float* log_s     = (const float*)d_in[2];
    const float* pos_w     = (const float*)d_in[3];
    const float* pos_b     = (const float*)d_in[4];
    const float* w_lin_in  = (const float*)d_in[5];
    const float* w_val     = (const float*)d_in[6];
    const float* w_out     = (const float*)d_in[7];
    const float* w_lin_out = (const float*)d_in[8];
    float* out = (float*)d_out;

    cudaFuncSetAttribute(k_attn, cudaFuncAttributeMaxDynamicSharedMemorySize, ATT_SMEM);

    dim3 gi(14, WCHUNK);
    k_init_w3j_a<<<gi, 128>>>();
    k_init_w3j_b<<<14, 128>>>();
    k_init_small<<<1,32>>>(w_lin_in, w_val, w_out, w_lin_out);
    k_prep<<<(NB*NN)/8, 256>>>(feat, sh_lr, log_s, pos_w, pos_b);
    k_trans<<<dim3(NN/64, NB), 256>>>();
    k_attn<<<dim3(NN/128, NB), 256, ATT_SMEM>>>();
    k_out<<<(NB*NN)/8, 256>>>(feat, out);
}